// round 6
// baseline (speedup 1.0000x reference)
#include <cuda_runtime.h>
#include <math.h>

// Problem constants
#define PB_N0 2048
#define PB_N1 32768
#define PB_N2 524288
#define PB_C  16
#define PB_D  128
#define PB_H  128
#define PB_ED 8

// ---------------- scratch (device globals; no runtime allocation) ----------
__device__ float g_pooled[(size_t)PB_N1 * PB_H];  // 16.8 MB (reused at level 0)
__device__ float g_h1[(size_t)PB_N1 * PB_H];      // 16.8 MB
__device__ float g_Wc[3 * PB_D * PB_H];           // W_fe @ W_x[l][:128]
__device__ float g_bias[3 * PB_H];                // b_fe @ W_x[l][:128] + b_r[l]

// ---------------- tf32 / math helpers --------------------------------------
__device__ __forceinline__ unsigned f2tf(float f) {
    unsigned r; asm("cvt.rna.tf32.f32 %0, %1;" : "=r"(r) : "f"(f)); return r;
}
__device__ __forceinline__ void mma8(float4& d, const unsigned a[4],
                                     unsigned b0, unsigned b1) {
    asm volatile(
        "mma.sync.aligned.m16n8k8.row.col.f32.tf32.tf32.f32 "
        "{%0,%1,%2,%3},{%4,%5,%6,%7},{%8,%9},{%0,%1,%2,%3};"
        : "+f"(d.x), "+f"(d.y), "+f"(d.z), "+f"(d.w)
        : "r"(a[0]), "r"(a[1]), "r"(a[2]), "r"(a[3]), "r"(b0), "r"(b1));
}
__device__ __forceinline__ float fast_tanh(float x) {
    float e = __expf(2.f * x);
    return 1.f - __fdividef(2.f, e + 1.f);
}

// ---------------- fragment-order smem layouts -------------------------------
// X chunk (128 rows x 16 K) in A-fragment order: 2048 u32 = 8KB
//   u32 addr = ((tile_m*2 + ks)*32 + lane)*4 + e
__device__ __forceinline__ int xfrag_idx(int r, int c) {
    int tile = r >> 4, rm = r & 15, kc = c & 7;
    return (((tile << 1) + (c >> 3)) * 32 + (rm & 7) * 4 + (kc & 3)) * 4
         + ((rm >> 3) + ((kc >> 2) << 1));
}
// W chunk (16 K x 128 cols) in B-fragment order: 2048 u32 = 8KB
//   u32 addr = ((ks*16 + tile_n)*32 + lane)*2 + e
__device__ __forceinline__ int wfrag_idx(int k, int c) {
    return (((k >> 3) * 16 + (c >> 3)) * 32 + (c & 7) * 4 + (k & 3)) * 2
         + ((k >> 2) & 1);
}
// full 128x128 hidden tile in A-fragment order (16384 u32 = 64KB):
//   u32 addr = ((tile_m*16 + kc)*32 + lane)*4 + e
__device__ __forceinline__ int hfrag_idx(int r, int c) {
    int tile = r >> 4, rm = r & 15;
    return ((tile * 16 + (c >> 3)) * 32 + (rm & 7) * 4 + (c & 3)) * 4
         + ((rm >> 3) + 2 * ((c >> 2) & 1));
}

// ---------------- pipelined global loads / frag stores ----------------------
__device__ __forceinline__ void loadX(const float* A, size_t rowbase, int kb,
                                      int t, float4& xa, float4& xb) {
    int f = t, r = f >> 2, c4 = (f & 3) * 4;
    xa = *(const float4*)(A + (rowbase + r) * 128 + kb + c4);
    f = t + 256; r = f >> 2; c4 = (f & 3) * 4;
    xb = *(const float4*)(A + (rowbase + r) * 128 + kb + c4);
}
__device__ __forceinline__ void loadW(const float* W, int kb,
                                      int t, float4& wa, float4& wb) {
    int f = t, r = f >> 5, c4 = (f & 31) * 4;
    wa = *(const float4*)(W + (size_t)(kb + r) * 128 + c4);
    f = t + 256; r = f >> 5; c4 = (f & 31) * 4;
    wb = *(const float4*)(W + (size_t)(kb + r) * 128 + c4);
}
// consecutive c -> lane+1 -> u32 addr +4
__device__ __forceinline__ void storeXf(unsigned* Xb, int t,
                                        const float4& xa, const float4& xb) {
    int f = t, r = f >> 2, c4 = (f & 3) * 4;
    unsigned* d0 = Xb + xfrag_idx(r, c4);
    d0[0] = f2tf(xa.x); d0[4] = f2tf(xa.y); d0[8] = f2tf(xa.z); d0[12] = f2tf(xa.w);
    f = t + 256; r = f >> 2; c4 = (f & 3) * 4;
    unsigned* d1 = Xb + xfrag_idx(r, c4);
    d1[0] = f2tf(xb.x); d1[4] = f2tf(xb.y); d1[8] = f2tf(xb.z); d1[12] = f2tf(xb.w);
}
// consecutive c -> lane+1 -> u32 addr +8 (wait: lane is (c&7)*4+(k&3), c+1 -> lane+4 -> +8)
__device__ __forceinline__ void storeWf(unsigned* Wb, int t,
                                        const float4& wa, const float4& wb) {
    int f = t, r = f >> 5, c4 = (f & 31) * 4;
    unsigned* d0 = Wb + wfrag_idx(r, c4);
    d0[0] = f2tf(wa.x); d0[8] = f2tf(wa.y); d0[16] = f2tf(wa.z); d0[24] = f2tf(wa.w);
    f = t + 256; r = f >> 5; c4 = (f & 31) * 4;
    unsigned* d1 = Wb + wfrag_idx(r, c4);
    d1[0] = f2tf(wb.x); d1[8] = f2tf(wb.y); d1[16] = f2tf(wb.z); d1[24] = f2tf(wb.w);
}

// one 16-K mma step; X/W in fragment order (vector LDS, conflict-free)
__device__ __forceinline__ void mma_chunk_f(float4 acc[4][4],
                                            const unsigned* Xb, const unsigned* Wb,
                                            int warpM, int warpN, int lane) {
    #pragma unroll
    for (int ks = 0; ks < 2; ++ks) {
        uint4 av[4]; uint2 bv[4];
        #pragma unroll
        for (int i = 0; i < 4; ++i)
            av[i] = ((const uint4*)Xb)[(((warpM * 4 + i) << 1) + ks) * 32 + lane];
        #pragma unroll
        for (int j = 0; j < 4; ++j)
            bv[j] = ((const uint2*)Wb)[(ks * 16 + warpN * 4 + j) * 32 + lane];
        #pragma unroll
        for (int i = 0; i < 4; ++i) {
            unsigned a[4] = {av[i].x, av[i].y, av[i].z, av[i].w};
            #pragma unroll
            for (int j = 0; j < 4; ++j) mma8(acc[i][j], a, bv[j].x, bv[j].y);
        }
    }
}

// ---------------- prep: Wc[l] = W_fe @ W_x[l][0:128,:] ---------------------
__global__ void prep_wc(const float* __restrict__ W_fe,
                        const float* __restrict__ W_x) {
    int l = blockIdx.x >> 7;
    int d = blockIdx.x & 127;
    int h = threadIdx.x;
    const float* wx = W_x + (size_t)l * 132 * 128;
    float acc = 0.f;
    #pragma unroll 8
    for (int k = 0; k < 128; ++k)
        acc += W_fe[d * 128 + k] * wx[k * 128 + h];
    g_Wc[((size_t)l * 128 + d) * 128 + h] = acc;
}

__global__ void prep_bias(const float* __restrict__ b_fe,
                          const float* __restrict__ W_x,
                          const float* __restrict__ b_r) {
    int l = blockIdx.x;
    int h = threadIdx.x;
    const float* wx = W_x + (size_t)l * 132 * 128;
    float acc = b_r[l * 128 + h];
    #pragma unroll 8
    for (int d = 0; d < 128; ++d)
        acc += b_fe[d] * wx[d * 128 + h];
    g_bias[l * 128 + h] = acc;
}

// ============================================================================
// fused_level: per block 128 child rows = 8 parents (warp w <-> parent w).
// ============================================================================
__global__ void __launch_bounds__(256, 2)
fused_level(const float* __restrict__ xin, const int* __restrict__ tvec,
            const float* __restrict__ tapg, const float* __restrict__ Wc,
            const float* __restrict__ biasg,
            const float* __restrict__ hin,
            const float* __restrict__ Ag, const float* __restrict__ Eg,
            const float* __restrict__ Weg,
            const float* __restrict__ Wg, const float* __restrict__ bgg,
            float* __restrict__ pooled)
{
    extern __shared__ unsigned char smraw[];
    unsigned* h2f = (unsigned*)smraw;                       // 16384 u = 64KB
    unsigned* Xs  = h2f + 16384;                            // 2 x 2048 u
    unsigned* Wks = Xs + 2 * 2048;                          // 2 x 2048 u (8KB each)
    float* taps   = (float*)(Wks + 2 * 2048);               // [4][128]
    float* bgs    = taps + 4 * 128;                         // [128]
    float* biass  = bgs + 128;                              // [128]
    int*   ts     = (int*)(biass + 128);                    // [128]

    const int t = threadIdx.x;
    const int lane = t & 31, wid = t >> 5;
    const int warpM = wid >> 2, warpN = wid & 3;
    const int g = lane >> 2, tg = lane & 3;
    const size_t rowbase = (size_t)blockIdx.x * 128;

    if (t < 128) bgs[t] = bgg[t];

    float4 acc[4][4];
    float gg[2][2][2];   // [c8][k8][k4] gate values for this lane's parent

    if (xin) {
        if (t < 128) { biass[t] = biasg[t]; ts[t] = tvec[rowbase + t]; }
        taps[t] = tapg[t]; taps[t + 256] = tapg[t + 256];

        #pragma unroll
        for (int i = 0; i < 4; ++i)
            #pragma unroll
            for (int j = 0; j < 4; ++j) acc[i][j] = make_float4(0.f, 0.f, 0.f, 0.f);

        float4 xa, xb, wa, wb;
        loadX(xin, rowbase, 0, t, xa, xb);
        loadW(Wc, 0, t, wa, wb);
        #pragma unroll
        for (int it = 0; it < 8; ++it) {
            unsigned* Xb = Xs + (it & 1) * 2048;
            unsigned* Wb = Wks + (it & 1) * 2048;
            storeXf(Xb, t, xa, xb);
            storeWf(Wb, t, wa, wb);
            __syncthreads();
            if (it < 7) {
                loadX(xin, rowbase, (it + 1) * 16, t, xa, xb);
                loadW(Wc, (it + 1) * 16, t, wa, wb);
            }
            mma_chunk_f(acc, Xb, Wb, warpM, warpN, lane);
        }

        // gates (register-resident)
        {
            const size_t ebase = (size_t)blockIdx.x * 2048 + wid * 256;
            float we0 = Weg[0], we1 = Weg[1], we2 = Weg[2], we3 = Weg[3];
            float we4 = Weg[4], we5 = Weg[5], we6 = Weg[6], we7 = Weg[7];
            #pragma unroll
            for (int c8 = 0; c8 < 2; ++c8)
                #pragma unroll
                for (int k8 = 0; k8 < 2; ++k8)
                    #pragma unroll
                    for (int k4 = 0; k4 < 2; ++k4) {
                        int c = g + 8 * c8, k = tg + 4 * k4 + 8 * k8;
                        const float* e = Eg + (ebase + c * 16 + k) * 8;
                        float4 e0 = *(const float4*)(e);
                        float4 e1 = *(const float4*)(e + 4);
                        float s = e0.x * we0 + e0.y * we1 + e0.z * we2 + e0.w * we3
                                + e1.x * we4 + e1.y * we5 + e1.z * we6 + e1.w * we7;
                        gg[c8][k8][k4] = Ag[ebase + c * 16 + k] / (1.f + __expf(-s));
                    }
        }

        // epilogue: fast tanh -> h2f (fragment order)
        #pragma unroll
        for (int i = 0; i < 4; ++i) {
            int r0 = warpM * 64 + i * 16 + g, r1 = r0 + 8;
            const float* tap0 = taps + ts[r0] * 128;
            const float* tap1 = taps + ts[r1] * 128;
            #pragma unroll
            for (int j = 0; j < 4; ++j) {
                int c0 = warpN * 32 + j * 8 + tg * 2;
                h2f[hfrag_idx(r0, c0)]     = f2tf(fast_tanh(acc[i][j].x + biass[c0]     + tap0[c0]));
                h2f[hfrag_idx(r0, c0 + 1)] = f2tf(fast_tanh(acc[i][j].y + biass[c0 + 1] + tap0[c0 + 1]));
                h2f[hfrag_idx(r1, c0)]     = f2tf(fast_tanh(acc[i][j].z + biass[c0]     + tap1[c0]));
                h2f[hfrag_idx(r1, c0 + 1)] = f2tf(fast_tanh(acc[i][j].w + biass[c0 + 1] + tap1[c0 + 1]));
            }
        }
    } else {
        // load child hidden tile from global into fragment order
        #pragma unroll
        for (int u = 0; u < 16; ++u) {
            int f = t + u * 256; int r = f >> 5, c4 = (f & 31) * 4;
            float4 v = *(const float4*)(hin + (rowbase + r) * 128 + c4);
            unsigned* d = h2f + hfrag_idx(r, c4);
            d[0] = f2tf(v.x); d[4] = f2tf(v.y); d[8] = f2tf(v.z); d[12] = f2tf(v.w);
        }
        {
            const size_t ebase = (size_t)blockIdx.x * 2048 + wid * 256;
            float we0 = Weg[0], we1 = Weg[1], we2 = Weg[2], we3 = Weg[3];
            float we4 = Weg[4], we5 = Weg[5], we6 = Weg[6], we7 = Weg[7];
            #pragma unroll
            for (int c8 = 0; c8 < 2; ++c8)
                #pragma unroll
                for (int k8 = 0; k8 < 2; ++k8)
                    #pragma unroll
                    for (int k4 = 0; k4 < 2; ++k4) {
                        int c = g + 8 * c8, k = tg + 4 * k4 + 8 * k8;
                        const float* e = Eg + (ebase + c * 16 + k) * 8;
                        float4 e0 = *(const float4*)(e);
                        float4 e1 = *(const float4*)(e + 4);
                        float s = e0.x * we0 + e0.y * we1 + e0.z * we2 + e0.w * we3
                                + e1.x * we4 + e1.y * we5 + e1.z * we6 + e1.w * we7;
                        gg[c8][k8][k4] = Ag[ebase + c * 16 + k] / (1.f + __expf(-s));
                    }
        }
    }
    __syncthreads();   // h2f complete

    // Phase C: per-parent mix M_p = G_p @ child_h_p  (warp wid = parent)
    {
        float4 macc[16];
        #pragma unroll
        for (int j = 0; j < 16; ++j) macc[j] = make_float4(0.f, 0.f, 0.f, 0.f);
        int p = wid;
        #pragma unroll
        for (int ks = 0; ks < 2; ++ks) {
            unsigned a[4];
            a[0] = f2tf(gg[0][ks][0]);
            a[1] = f2tf(gg[1][ks][0]);
            a[2] = f2tf(gg[0][ks][1]);
            a[3] = f2tf(gg[1][ks][1]);
            #pragma unroll
            for (int j = 0; j < 16; ++j) {
                unsigned b0 = h2f[hfrag_idx(p * 16 + ks * 8 + tg,     j * 8 + g)];
                unsigned b1 = h2f[hfrag_idx(p * 16 + ks * 8 + tg + 4, j * 8 + g)];
                mma8(macc[j], a, b0, b1);
            }
        }
        __syncwarp();
        #pragma unroll
        for (int j = 0; j < 16; ++j) {
            int c0 = j * 8 + tg * 2;
            h2f[hfrag_idx(p * 16 + g,     c0)]     = f2tf(macc[j].x);
            h2f[hfrag_idx(p * 16 + g,     c0 + 1)] = f2tf(macc[j].y);
            h2f[hfrag_idx(p * 16 + g + 8, c0)]     = f2tf(macc[j].z);
            h2f[hfrag_idx(p * 16 + g + 8, c0 + 1)] = f2tf(macc[j].w);
        }
    }
    __syncthreads();

    // Phase D: Hc = relu(M @ Wg + bg); maxpool over each parent's 16 rows
    #pragma unroll
    for (int i = 0; i < 4; ++i)
        #pragma unroll
        for (int j = 0; j < 4; ++j) acc[i][j] = make_float4(0.f, 0.f, 0.f, 0.f);

    {
        float4 wa, wb;
        loadW(Wg, 0, t, wa, wb);
        #pragma unroll
        for (int it = 0; it < 8; ++it) {
            unsigned* Wb = Wks + (it & 1) * 2048;
            storeWf(Wb, t, wa, wb);
            __syncthreads();
            if (it < 7) loadW(Wg, (it + 1) * 16, t, wa, wb);
            #pragma unroll
            for (int ks = 0; ks < 2; ++ks) {
                uint4 av[4]; uint2 bv[4];
                #pragma unroll
                for (int i = 0; i < 4; ++i)
                    av[i] = ((const uint4*)h2f)[((warpM * 4 + i) * 16 + it * 2 + ks) * 32 + lane];
                #pragma unroll
                for (int j = 0; j < 4; ++j)
                    bv[j] = ((const uint2*)Wb)[(ks * 16 + warpN * 4 + j) * 32 + lane];
                #pragma unroll
                for (int i = 0; i < 4; ++i) {
                    unsigned a[4] = {av[i].x, av[i].y, av[i].z, av[i].w};
                    #pragma unroll
                    for (int j = 0; j < 4; ++j) mma8(acc[i][j], a, bv[j].x, bv[j].y);
                }
            }
        }
    }

    // relu + 16-row maxpool (m-tile i == parent warpM*4+i exactly)
    #pragma unroll
    for (int i = 0; i < 4; ++i) {
        size_t parent = (size_t)blockIdx.x * 8 + warpM * 4 + i;
        #pragma unroll
        for (int j = 0; j < 4; ++j) {
            int c0 = warpN * 32 + j * 8 + tg * 2;
            float b0 = bgs[c0], b1 = bgs[c0 + 1];
            float v0 = fmaxf(fmaxf(acc[i][j].x + b0, acc[i][j].z + b0), 0.f);
            float v1 = fmaxf(fmaxf(acc[i][j].y + b1, acc[i][j].w + b1), 0.f);
            #pragma unroll
            for (int off = 16; off >= 4; off >>= 1) {
                v0 = fmaxf(v0, __shfl_xor_sync(0xffffffffu, v0, off));
                v1 = fmaxf(v1, __shfl_xor_sync(0xffffffffu, v1, off));
            }
            if (lane < 4)
                *(float2*)(pooled + parent * 128 + c0) = make_float2(v0, v1);
        }
    }
}

// ============================================================================
// gemm_tanh: out = tanh(A0 @ W0 + A1 @ W1 + bias + typerow[t]) , tf32 mma
// ============================================================================
__global__ void __launch_bounds__(256, 2)
gemm_tanh(const float* __restrict__ A0g, const float* __restrict__ W0,
          const float* __restrict__ A1g, const float* __restrict__ W1,
          const float* __restrict__ biasg, const float* __restrict__ tapg,
          const int* __restrict__ tvec, float* __restrict__ out)
{
    __shared__ __align__(16) unsigned Xs[2][2048];
    __shared__ __align__(16) unsigned Wks[2][2048];
    __shared__ float taps[4][128];
    __shared__ float biass[128];
    __shared__ int ts[128];

    const int t = threadIdx.x;
    const int lane = t & 31, wid = t >> 5;
    const int warpM = wid >> 2, warpN = wid & 3;
    const int g = lane >> 2, tg = lane & 3;
    const size_t rowbase = (size_t)blockIdx.x * 128;

    if (t < 128) { biass[t] = biasg[t]; ts[t] = tvec[rowbase + t]; }
    ((float*)taps)[t] = tapg[t]; ((float*)taps)[t + 256] = tapg[t + 256];

    const float* Aseg[2] = {A0g, A1g};
    const float* Wseg[2] = {W0, W1};

    float4 acc[4][4];
    #pragma unroll
    for (int i = 0; i < 4; ++i)
        #pragma unroll
        for (int j = 0; j < 4; ++j) acc[i][j] = make_float4(0.f, 0.f, 0.f, 0.f);

    float4 xa, xb, wa, wb;
    loadX(A0g, rowbase, 0, t, xa, xb);
    loadW(W0, 0, t, wa, wb);
    #pragma unroll
    for (int it = 0; it < 16; ++it) {
        unsigned* Xb = Xs[it & 1];
        unsigned* Wb = Wks[it & 1];
        storeXf(Xb, t, xa, xb);
        storeWf(Wb, t, wa, wb);
        __syncthreads();
        if (it < 15) {
            int nit = it + 1;
            loadX(Aseg[nit >> 3], rowbase, (nit & 7) * 16, t, xa, xb);
            loadW(Wseg[nit >> 3], (nit & 7) * 16, t, wa, wb);
        }
        mma_chunk_f(acc, Xb, Wb, warpM, warpN, lane);
    }

    #pragma unroll
    for (int i = 0; i < 4; ++i) {
        int r0 = warpM * 64 + i * 16 + g, r1 = r0 + 8;
        const float* tap0 = taps[ts[r0]];
        const float* tap1 = taps[ts[r1]];
        #pragma unroll
        for (int j = 0; j < 4; ++j) {
            int c0 = warpN * 32 + j * 8 + tg * 2;
            float o0 = fast_tanh(acc[i][j].x + biass[c0]     + tap0[c0]);
            float o1 = fast_tanh(acc[i][j].y + biass[c0 + 1] + tap0[c0 + 1]);
            float o2 = fast_tanh(acc[i][j].z + biass[c0]     + tap1[c0]);
            float o3 = fast_tanh(acc[i][j].w + biass[c0 + 1] + tap1[c0 + 1]);
            *(float2*)(out + (rowbase + r0) * 128 + c0) = make_float2(o0, o1);
            *(float2*)(out + (rowbase + r1) * 128 + c0) = make_float2(o2, o3);
        }
    }
}

// ---------------- launch -----------------------------------------------
extern "C" void kernel_launch(void* const* d_in, const int* in_sizes, int n_in,
                              void* d_out, int out_size) {
    const float* x0   = (const float*)d_in[0];
    const float* x1   = (const float*)d_in[1];
    const float* x2   = (const float*)d_in[2];
    const int*   t0   = (const int*)  d_in[3];
    const int*   t1   = (const int*)  d_in[4];
    const int*   t2   = (const int*)  d_in[5];
    const float* A0   = (const float*)d_in[6];
    const float* A1   = (const float*)d_in[7];
    const float* E0   = (const float*)d_in[8];
    const float* E1   = (const float*)d_in[9];
    const float* W_fe = (const float*)d_in[10];
    const float* b_fe = (const float*)d_in[11];
    const float* W_x  = (const float*)d_in[12];
    const float* W_h  = (const float*)d_in[13];
    const float* W_e  = (const float*)d_in[14];
    const float* W_g  = (const float*)d_in[15];
    const float* b_g  = (const float*)d_in[16];
    const float* b_r  = (const float*)d_in[17];

    float *pooled, *h1, *Wc, *bias;
    cudaGetSymbolAddress((void**)&pooled, g_pooled);
    cudaGetSymbolAddress((void**)&h1,     g_h1);
    cudaGetSymbolAddress((void**)&Wc,     g_Wc);
    cudaGetSymbolAddress((void**)&bias,   g_bias);

    const int SMEMSZ = (16384 + 2 * 2048 + 2 * 2048) * 4
                     + (4 * 128 + 128 + 128 + 128) * 4;   // 101,888 B
    cudaFuncSetAttribute(fused_level, cudaFuncAttributeMaxDynamicSharedMemorySize, SMEMSZ);

    // fold W_fe/b_fe into per-level weights
    prep_wc<<<3 * 128, 128>>>(W_fe, W_x);
    prep_bias<<<3, 128>>>(b_fe, W_x, b_r);

    // level 2 + level 1 GNN fused: x2 -> h2 (smem) -> gate/mix -> relu GEMM -> pooled1
    fused_level<<<PB_N2 / 128, 256, SMEMSZ>>>(
        x2, t2, W_x + 2 * 132 * 128 + 128 * 128, Wc + 2 * 128 * 128, bias + 2 * 128,
        nullptr, A1, E1, W_e + 8, W_g + 128 * 128, b_g + 128, pooled);

    // h1 = tanh(x1 @ Wc1 + pooled1 @ W_h1 + bias1 + typerow)
    gemm_tanh<<<PB_N1 / 128, 256>>>(
        x1, Wc + 128 * 128, pooled, W_h + 128 * 128,
        bias + 128, W_x + 132 * 128 + 128 * 128, t1, h1);

    // level 0 GNN fused (child hidden loaded from h1)
    fused_level<<<PB_N1 / 128, 256, SMEMSZ>>>(
        nullptr, nullptr, nullptr, nullptr, nullptr,
        h1, A0, E0, W_e, W_g, b_g, pooled);

    // roots: h0 -> d_out
    gemm_tanh<<<PB_N0 / 128, 256>>>(
        x0, Wc, pooled, W_h,
        bias, W_x + 128 * 128, t0, (float*)d_out);
}

// round 7
// speedup vs baseline: 2.1588x; 2.1588x over previous
#include <cuda_runtime.h>
#include <math.h>

// Problem constants
#define PB_N0 2048
#define PB_N1 32768
#define PB_N2 524288
#define PB_C  16
#define PB_D  128
#define PB_H  128
#define PB_ED 8

#define WS_STRIDE 132   // padded stride for 128-wide smem tiles
#define XS_STRIDE 20    // padded stride for 16-wide K chunks (conflict-free)

// ---------------- scratch (device globals; no runtime allocation) ----------
__device__ float g_pooled[(size_t)PB_N1 * PB_H];  // 16.8 MB (reused at level 0)
__device__ float g_h1[(size_t)PB_N1 * PB_H];      // 16.8 MB
__device__ float g_Wc[3 * PB_D * PB_H];           // W_fe @ W_x[l][:128]
__device__ float g_bias[3 * PB_H];                // b_fe @ W_x[l][:128] + b_r[l]

// ---------------- tf32 / math helpers ---------------------------------------
__device__ __forceinline__ unsigned f2tf(float f) {
    unsigned r; asm("cvt.rna.tf32.f32 %0, %1;" : "=r"(r) : "f"(f)); return r;
}
__device__ __forceinline__ void mma8(float4& d, const unsigned a[4],
                                     unsigned b0, unsigned b1) {
    asm volatile(
        "mma.sync.aligned.m16n8k8.row.col.f32.tf32.tf32.f32 "
        "{%0,%1,%2,%3},{%4,%5,%6,%7},{%8,%9},{%0,%1,%2,%3};"
        : "+f"(d.x), "+f"(d.y), "+f"(d.z), "+f"(d.w)
        : "r"(a[0]), "r"(a[1]), "r"(a[2]), "r"(a[3]), "r"(b0), "r"(b1));
}
__device__ __forceinline__ float fast_tanh(float x) {
    float e = __expf(2.f * x);
    return 1.f - __fdividef(2.f, e + 1.f);
}

// store a prefetched X chunk (regs -> smem, tf32)
__device__ __forceinline__ void storeX(unsigned* Xb, int t,
                                       const float4& xa, const float4& xb) {
    int f = t, r = f >> 2, c4 = (f & 3) * 4;
    unsigned* d = Xb + r * XS_STRIDE + c4;
    d[0] = f2tf(xa.x); d[1] = f2tf(xa.y); d[2] = f2tf(xa.z); d[3] = f2tf(xa.w);
    f = t + 256; r = f >> 2; c4 = (f & 3) * 4;
    d = Xb + r * XS_STRIDE + c4;
    d[0] = f2tf(xb.x); d[1] = f2tf(xb.y); d[2] = f2tf(xb.z); d[3] = f2tf(xb.w);
}
__device__ __forceinline__ void storeW(unsigned* Wb, int t,
                                       const float4& wa, const float4& wb) {
    int f = t, r = f >> 5, c4 = (f & 31) * 4;
    unsigned* d = Wb + r * WS_STRIDE + c4;
    d[0] = f2tf(wa.x); d[1] = f2tf(wa.y); d[2] = f2tf(wa.z); d[3] = f2tf(wa.w);
    f = t + 256; r = f >> 5; c4 = (f & 31) * 4;
    d = Wb + r * WS_STRIDE + c4;
    d[0] = f2tf(wb.x); d[1] = f2tf(wb.y); d[2] = f2tf(wb.z); d[3] = f2tf(wb.w);
}
__device__ __forceinline__ void loadX(const float* A, size_t rowbase, int kb,
                                      int t, float4& xa, float4& xb) {
    int f = t, r = f >> 2, c4 = (f & 3) * 4;
    xa = *(const float4*)(A + (rowbase + r) * 128 + kb + c4);
    f = t + 256; r = f >> 2; c4 = (f & 3) * 4;
    xb = *(const float4*)(A + (rowbase + r) * 128 + kb + c4);
}
__device__ __forceinline__ void loadW(const float* W, int kb,
                                      int t, float4& wa, float4& wb) {
    int f = t, r = f >> 5, c4 = (f & 31) * 4;
    wa = *(const float4*)(W + (size_t)(kb + r) * 128 + c4);
    f = t + 256; r = f >> 5; c4 = (f & 31) * 4;
    wb = *(const float4*)(W + (size_t)(kb + r) * 128 + c4);
}

// one 16-K-deep mma step on a 128x128 tile (per-warp 64x32 sub-tile)
__device__ __forceinline__ void mma_chunk(float4 acc[4][4],
                                          const unsigned* Xb, int xstride,
                                          const unsigned* Wb,
                                          int warpM, int warpN, int g, int tg) {
    #pragma unroll
    for (int ks = 0; ks < 2; ++ks) {
        int k0 = ks * 8;
        unsigned a[4][4], b[4][2];
        #pragma unroll
        for (int i = 0; i < 4; ++i) {
            int rb = warpM * 64 + i * 16;
            a[i][0] = Xb[(rb + g) * xstride + k0 + tg];
            a[i][1] = Xb[(rb + g + 8) * xstride + k0 + tg];
            a[i][2] = Xb[(rb + g) * xstride + k0 + tg + 4];
            a[i][3] = Xb[(rb + g + 8) * xstride + k0 + tg + 4];
        }
        #pragma unroll
        for (int j = 0; j < 4; ++j) {
            int col = warpN * 32 + j * 8 + g;
            b[j][0] = Wb[(k0 + tg) * WS_STRIDE + col];
            b[j][1] = Wb[(k0 + tg + 4) * WS_STRIDE + col];
        }
        #pragma unroll
        for (int i = 0; i < 4; ++i)
            #pragma unroll
            for (int j = 0; j < 4; ++j) mma8(acc[i][j], a[i], b[j][0], b[j][1]);
    }
}

// ---------------- prep: Wc[l] = W_fe @ W_x[l][0:128,:] ---------------------
__global__ void prep_wc(const float* __restrict__ W_fe,
                        const float* __restrict__ W_x) {
    int l = blockIdx.x >> 7;
    int d = blockIdx.x & 127;
    int h = threadIdx.x;
    const float* wx = W_x + (size_t)l * 132 * 128;
    float acc = 0.f;
    #pragma unroll 8
    for (int k = 0; k < 128; ++k)
        acc += W_fe[d * 128 + k] * wx[k * 128 + h];
    g_Wc[((size_t)l * 128 + d) * 128 + h] = acc;
}

__global__ void prep_bias(const float* __restrict__ b_fe,
                          const float* __restrict__ W_x,
                          const float* __restrict__ b_r) {
    int l = blockIdx.x;
    int h = threadIdx.x;
    const float* wx = W_x + (size_t)l * 132 * 128;
    float acc = b_r[l * 128 + h];
    #pragma unroll 8
    for (int d = 0; d < 128; ++d)
        acc += b_fe[d] * wx[d * 128 + h];
    g_bias[l * 128 + h] = acc;
}

// ============================================================================
// fused_level: per block 128 child rows = 8 parents (warp w <-> parent w).
//   A: child_h = tanh(xin @ Wc + bias + typerow) -> smem tf32  (or load hin)
//   gates: each lane computes its 8 mma-A-fragment gate values in registers
//   C: M_p = G_p @ child_h_p per warp (writes back into h2s)
//   D: Hc = relu(M @ Wg + bg); 16-row maxpool -> pooled
// Single-sync double-buffered K pipeline on A and D.
// ============================================================================
__global__ void __launch_bounds__(256, 2)
fused_level(const float* __restrict__ xin, const int* __restrict__ tvec,
            const float* __restrict__ tapg, const float* __restrict__ Wc,
            const float* __restrict__ biasg,
            const float* __restrict__ hin,
            const float* __restrict__ Ag, const float* __restrict__ Eg,
            const float* __restrict__ Weg,
            const float* __restrict__ Wg, const float* __restrict__ bgg,
            float* __restrict__ pooled)
{
    extern __shared__ unsigned char smraw[];
    unsigned* h2s = (unsigned*)smraw;                       // [128][132]
    unsigned* Xs  = h2s + 128 * WS_STRIDE;                  // [2][128][20]
    unsigned* Wks = Xs + 2 * 128 * XS_STRIDE;               // [2][16][132]
    float* taps   = (float*)(Wks + 2 * 16 * WS_STRIDE);     // [4][128]
    float* bgs    = taps + 4 * 128;                         // [128]
    float* biass  = bgs + 128;                              // [128]
    int*   ts     = (int*)(biass + 128);                    // [128]

    const int t = threadIdx.x;
    const int lane = t & 31, wid = t >> 5;
    const int warpM = wid >> 2, warpN = wid & 3;
    const int g = lane >> 2, tg = lane & 3;
    const size_t rowbase = (size_t)blockIdx.x * 128;

    if (t < 128) bgs[t] = bgg[t];

    float4 acc[4][4];
    float gg[2][2][2];   // [c8][k8][k4] gate values for this lane's parent

    if (xin) {
        if (t < 128) { biass[t] = biasg[t]; ts[t] = tvec[rowbase + t]; }
        taps[t] = tapg[t]; taps[t + 256] = tapg[t + 256];

        #pragma unroll
        for (int i = 0; i < 4; ++i)
            #pragma unroll
            for (int j = 0; j < 4; ++j) acc[i][j] = make_float4(0.f, 0.f, 0.f, 0.f);

        float4 xa, xb, wa, wb;
        loadX(xin, rowbase, 0, t, xa, xb);
        loadW(Wc, 0, t, wa, wb);
        #pragma unroll
        for (int it = 0; it < 8; ++it) {
            unsigned* Xb = Xs + (it & 1) * 128 * XS_STRIDE;
            unsigned* Wb = Wks + (it & 1) * 16 * WS_STRIDE;
            storeX(Xb, t, xa, xb);
            storeW(Wb, t, wa, wb);
            __syncthreads();
            if (it < 7) {
                loadX(xin, rowbase, (it + 1) * 16, t, xa, xb);
                loadW(Wc, (it + 1) * 16, t, wa, wb);
            }
            mma_chunk(acc, Xb, XS_STRIDE, Wb, warpM, warpN, g, tg);
        }

        // gates (register-resident, loads overlap epilogue latency below)
        {
            const size_t ebase = (size_t)blockIdx.x * 2048 + wid * 256;
            float we0 = Weg[0], we1 = Weg[1], we2 = Weg[2], we3 = Weg[3];
            float we4 = Weg[4], we5 = Weg[5], we6 = Weg[6], we7 = Weg[7];
            #pragma unroll
            for (int c8 = 0; c8 < 2; ++c8)
                #pragma unroll
                for (int k8 = 0; k8 < 2; ++k8)
                    #pragma unroll
                    for (int k4 = 0; k4 < 2; ++k4) {
                        int c = g + 8 * c8, k = tg + 4 * k4 + 8 * k8;
                        const float* e = Eg + (ebase + c * 16 + k) * 8;
                        float4 e0 = *(const float4*)(e);
                        float4 e1 = *(const float4*)(e + 4);
                        float s = e0.x * we0 + e0.y * we1 + e0.z * we2 + e0.w * we3
                                + e1.x * we4 + e1.y * we5 + e1.z * we6 + e1.w * we7;
                        gg[c8][k8][k4] = Ag[ebase + c * 16 + k] / (1.f + __expf(-s));
                    }
        }

        // epilogue: fast tanh -> h2s (tf32 bits)
        #pragma unroll
        for (int i = 0; i < 4; ++i) {
            int r0 = warpM * 64 + i * 16 + g, r1 = r0 + 8;
            const float* tap0 = taps + ts[r0] * 128;
            const float* tap1 = taps + ts[r1] * 128;
            #pragma unroll
            for (int j = 0; j < 4; ++j) {
                int c0 = warpN * 32 + j * 8 + tg * 2;
                h2s[r0 * WS_STRIDE + c0]     = f2tf(fast_tanh(acc[i][j].x + biass[c0]     + tap0[c0]));
                h2s[r0 * WS_STRIDE + c0 + 1] = f2tf(fast_tanh(acc[i][j].y + biass[c0 + 1] + tap0[c0 + 1]));
                h2s[r1 * WS_STRIDE + c0]     = f2tf(fast_tanh(acc[i][j].z + biass[c0]     + tap1[c0]));
                h2s[r1 * WS_STRIDE + c0 + 1] = f2tf(fast_tanh(acc[i][j].w + biass[c0 + 1] + tap1[c0 + 1]));
            }
        }
    } else {
        // load child hidden tile from global
        #pragma unroll
        for (int u = 0; u < 16; ++u) {
            int f = t + u * 256; int r = f >> 5, c4 = (f & 31) * 4;
            float4 v = *(const float4*)(hin + (rowbase + r) * 128 + c4);
            unsigned* d = h2s + r * WS_STRIDE + c4;
            d[0] = f2tf(v.x); d[1] = f2tf(v.y); d[2] = f2tf(v.z); d[3] = f2tf(v.w);
        }
        {
            const size_t ebase = (size_t)blockIdx.x * 2048 + wid * 256;
            float we0 = Weg[0], we1 = Weg[1], we2 = Weg[2], we3 = Weg[3];
            float we4 = Weg[4], we5 = Weg[5], we6 = Weg[6], we7 = Weg[7];
            #pragma unroll
            for (int c8 = 0; c8 < 2; ++c8)
                #pragma unroll
                for (int k8 = 0; k8 < 2; ++k8)
                    #pragma unroll
                    for (int k4 = 0; k4 < 2; ++k4) {
                        int c = g + 8 * c8, k = tg + 4 * k4 + 8 * k8;
                        const float* e = Eg + (ebase + c * 16 + k) * 8;
                        float4 e0 = *(const float4*)(e);
                        float4 e1 = *(const float4*)(e + 4);
                        float s = e0.x * we0 + e0.y * we1 + e0.z * we2 + e0.w * we3
                                + e1.x * we4 + e1.y * we5 + e1.z * we6 + e1.w * we7;
                        gg[c8][k8][k4] = Ag[ebase + c * 16 + k] / (1.f + __expf(-s));
                    }
        }
    }
    __syncthreads();   // h2s complete, all warps may read any parent rows

    // Phase C: per-parent mix M_p = G_p @ child_h_p  (warp wid = parent)
    {
        float4 macc[16];
        #pragma unroll
        for (int j = 0; j < 16; ++j) macc[j] = make_float4(0.f, 0.f, 0.f, 0.f);
        int p = wid;
        #pragma unroll
        for (int ks = 0; ks < 2; ++ks) {
            unsigned a[4];
            a[0] = f2tf(gg[0][ks][0]);
            a[1] = f2tf(gg[1][ks][0]);
            a[2] = f2tf(gg[0][ks][1]);
            a[3] = f2tf(gg[1][ks][1]);
            #pragma unroll
            for (int j = 0; j < 16; ++j) {
                unsigned b0 = h2s[(p * 16 + ks * 8 + tg) * WS_STRIDE + j * 8 + g];
                unsigned b1 = h2s[(p * 16 + ks * 8 + tg + 4) * WS_STRIDE + j * 8 + g];
                mma8(macc[j], a, b0, b1);
            }
        }
        __syncwarp();
        #pragma unroll
        for (int j = 0; j < 16; ++j) {
            int c0 = j * 8 + tg * 2;
            h2s[(p * 16 + g) * WS_STRIDE + c0]         = f2tf(macc[j].x);
            h2s[(p * 16 + g) * WS_STRIDE + c0 + 1]     = f2tf(macc[j].y);
            h2s[(p * 16 + g + 8) * WS_STRIDE + c0]     = f2tf(macc[j].z);
            h2s[(p * 16 + g + 8) * WS_STRIDE + c0 + 1] = f2tf(macc[j].w);
        }
    }
    __syncthreads();

    // Phase D: Hc = relu(M @ Wg + bg); maxpool over each parent's 16 rows
    #pragma unroll
    for (int i = 0; i < 4; ++i)
        #pragma unroll
        for (int j = 0; j < 4; ++j) acc[i][j] = make_float4(0.f, 0.f, 0.f, 0.f);

    {
        float4 wa, wb;
        loadW(Wg, 0, t, wa, wb);
        #pragma unroll
        for (int it = 0; it < 8; ++it) {
            unsigned* Wb = Wks + (it & 1) * 16 * WS_STRIDE;
            storeW(Wb, t, wa, wb);
            __syncthreads();
            if (it < 7) loadW(Wg, (it + 1) * 16, t, wa, wb);
            #pragma unroll
            for (int ks = 0; ks < 2; ++ks) {
                int k0 = it * 16 + ks * 8;
                unsigned a[4][4], b[4][2];
                #pragma unroll
                for (int i = 0; i < 4; ++i) {
                    int rb = warpM * 64 + i * 16;
                    a[i][0] = h2s[(rb + g) * WS_STRIDE + k0 + tg];
                    a[i][1] = h2s[(rb + g + 8) * WS_STRIDE + k0 + tg];
                    a[i][2] = h2s[(rb + g) * WS_STRIDE + k0 + tg + 4];
                    a[i][3] = h2s[(rb + g + 8) * WS_STRIDE + k0 + tg + 4];
                }
                #pragma unroll
                for (int j = 0; j < 4; ++j) {
                    int col = warpN * 32 + j * 8 + g;
                    b[j][0] = Wb[(ks * 8 + tg) * WS_STRIDE + col];
                    b[j][1] = Wb[(ks * 8 + tg + 4) * WS_STRIDE + col];
                }
                #pragma unroll
                for (int i = 0; i < 4; ++i)
                    #pragma unroll
                    for (int j = 0; j < 4; ++j) mma8(acc[i][j], a[i], b[j][0], b[j][1]);
            }
        }
    }

    // relu + 16-row maxpool (m-tile i == parent warpM*4+i exactly)
    #pragma unroll
    for (int i = 0; i < 4; ++i) {
        size_t parent = (size_t)blockIdx.x * 8 + warpM * 4 + i;
        #pragma unroll
        for (int j = 0; j < 4; ++j) {
            int c0 = warpN * 32 + j * 8 + tg * 2;
            float b0 = bgs[c0], b1 = bgs[c0 + 1];
            float v0 = fmaxf(fmaxf(acc[i][j].x + b0, acc[i][j].z + b0), 0.f);
            float v1 = fmaxf(fmaxf(acc[i][j].y + b1, acc[i][j].w + b1), 0.f);
            #pragma unroll
            for (int off = 16; off >= 4; off >>= 1) {
                v0 = fmaxf(v0, __shfl_xor_sync(0xffffffffu, v0, off));
                v1 = fmaxf(v1, __shfl_xor_sync(0xffffffffu, v1, off));
            }
            if (lane < 4)
                *(float2*)(pooled + parent * 128 + c0) = make_float2(v0, v1);
        }
    }
}

// ============================================================================
// gemm_tanh: out = tanh(A0 @ W0 + A1 @ W1 + bias + typerow[t]) , tf32 mma
// Single-sync double-buffered 16-chunk pipeline (2 segments x 8 chunks).
// ============================================================================
__global__ void __launch_bounds__(256, 2)
gemm_tanh(const float* __restrict__ A0g, const float* __restrict__ W0,
          const float* __restrict__ A1g, const float* __restrict__ W1,
          const float* __restrict__ biasg, const float* __restrict__ tapg,
          const int* __restrict__ tvec, float* __restrict__ out)
{
    __shared__ unsigned Xs[2][128 * XS_STRIDE];
    __shared__ unsigned Wks[2][16 * WS_STRIDE];
    __shared__ float taps[4][128];
    __shared__ float biass[128];
    __shared__ int ts[128];

    const int t = threadIdx.x;
    const int lane = t & 31, wid = t >> 5;
    const int warpM = wid >> 2, warpN = wid & 3;
    const int g = lane >> 2, tg = lane & 3;
    const size_t rowbase = (size_t)blockIdx.x * 128;

    if (t < 128) { biass[t] = biasg[t]; ts[t] = tvec[rowbase + t]; }
    ((float*)taps)[t] = tapg[t]; ((float*)taps)[t + 256] = tapg[t + 256];

    const float* Aseg[2] = {A0g, A1g};
    const float* Wseg[2] = {W0, W1};

    float4 acc[4][4];
    #pragma unroll
    for (int i = 0; i < 4; ++i)
        #pragma unroll
        for (int j = 0; j < 4; ++j) acc[i][j] = make_float4(0.f, 0.f, 0.f, 0.f);

    float4 xa, xb, wa, wb;
    loadX(A0g, rowbase, 0, t, xa, xb);
    loadW(W0, 0, t, wa, wb);
    #pragma unroll
    for (int it = 0; it < 16; ++it) {
        unsigned* Xb = Xs[it & 1];
        unsigned* Wb = Wks[it & 1];
        storeX(Xb, t, xa, xb);
        storeW(Wb, t, wa, wb);
        __syncthreads();
        if (it < 15) {
            int nit = it + 1;
            loadX(Aseg[nit >> 3], rowbase, (nit & 7) * 16, t, xa, xb);
            loadW(Wseg[nit >> 3], (nit & 7) * 16, t, wa, wb);
        }
        mma_chunk(acc, Xb, XS_STRIDE, Wb, warpM, warpN, g, tg);
    }

    #pragma unroll
    for (int i = 0; i < 4; ++i) {
        int r0 = warpM * 64 + i * 16 + g, r1 = r0 + 8;
        const float* tap0 = taps[ts[r0]];
        const float* tap1 = taps[ts[r1]];
        #pragma unroll
        for (int j = 0; j < 4; ++j) {
            int c0 = warpN * 32 + j * 8 + tg * 2;
            float o0 = fast_tanh(acc[i][j].x + biass[c0]     + tap0[c0]);
            float o1 = fast_tanh(acc[i][j].y + biass[c0 + 1] + tap0[c0 + 1]);
            float o2 = fast_tanh(acc[i][j].z + biass[c0]     + tap1[c0]);
            float o3 = fast_tanh(acc[i][j].w + biass[c0 + 1] + tap1[c0 + 1]);
            *(float2*)(out + (rowbase + r0) * 128 + c0) = make_float2(o0, o1);
            *(float2*)(out + (rowbase + r1) * 128 + c0) = make_float2(o2, o3);
        }
    }
}

// ---------------- launch -----------------------------------------------
extern "C" void kernel_launch(void* const* d_in, const int* in_sizes, int n_in,
                              void* d_out, int out_size) {
    const float* x0   = (const float*)d_in[0];
    const float* x1   = (const float*)d_in[1];
    const float* x2   = (const float*)d_in[2];
    const int*   t0   = (const int*)  d_in[3];
    const int*   t1   = (const int*)  d_in[4];
    const int*   t2   = (const int*)  d_in[5];
    const float* A0   = (const float*)d_in[6];
    const float* A1   = (const float*)d_in[7];
    const float* E0   = (const float*)d_in[8];
    const float* E1   = (const float*)d_in[9];
    const float* W_fe = (const float*)d_in[10];
    const float* b_fe = (const float*)d_in[11];
    const float* W_x  = (const float*)d_in[12];
    const float* W_h  = (const float*)d_in[13];
    const float* W_e  = (const float*)d_in[14];
    const float* W_g  = (const float*)d_in[15];
    const float* b_g  = (const float*)d_in[16];
    const float* b_r  = (const float*)d_in[17];

    float *pooled, *h1, *Wc, *bias;
    cudaGetSymbolAddress((void**)&pooled, g_pooled);
    cudaGetSymbolAddress((void**)&h1,     g_h1);
    cudaGetSymbolAddress((void**)&Wc,     g_Wc);
    cudaGetSymbolAddress((void**)&bias,   g_bias);

    const int SMEMSZ = (128 * WS_STRIDE + 2 * 128 * XS_STRIDE + 2 * 16 * WS_STRIDE) * 4
                     + (4 * 128 + 128 + 128 + 128) * 4;   // 108544 B
    cudaFuncSetAttribute(fused_level, cudaFuncAttributeMaxDynamicSharedMemorySize, SMEMSZ);

    // fold W_fe/b_fe into per-level weights
    prep_wc<<<3 * 128, 128>>>(W_fe, W_x);
    prep_bias<<<3, 128>>>(b_fe, W_x, b_r);

    // level 2 + level 1 GNN fused: x2 -> h2 (smem) -> gate/mix -> relu GEMM -> pooled1
    fused_level<<<PB_N2 / 128, 256, SMEMSZ>>>(
        x2, t2, W_x + 2 * 132 * 128 + 128 * 128, Wc + 2 * 128 * 128, bias + 2 * 128,
        nullptr, A1, E1, W_e + 8, W_g + 128 * 128, b_g + 128, pooled);

    // h1 = tanh(x1 @ Wc1 + pooled1 @ W_h1 + bias1 + typerow)
    gemm_tanh<<<PB_N1 / 128, 256>>>(
        x1, Wc + 128 * 128, pooled, W_h + 128 * 128,
        bias + 128, W_x + 132 * 128 + 128 * 128, t1, h1);

    // level 0 GNN fused (child hidden loaded from h1)
    fused_level<<<PB_N1 / 128, 256, SMEMSZ>>>(
        nullptr, nullptr, nullptr, nullptr, nullptr,
        h1, A0, E0, W_e, W_g, b_g, pooled);

    // roots: h0 -> d_out
    gemm_tanh<<<PB_N0 / 128, 256>>>(
        x0, Wc, pooled, W_h,
        bias, W_x + 128 * 128, t0, (float*)d_out);
}

// round 8
// speedup vs baseline: 2.2479x; 1.0412x over previous
#include <cuda_runtime.h>
#include <math.h>

// Problem constants
#define PB_N0 2048
#define PB_N1 32768
#define PB_N2 524288
#define PB_C  16
#define PB_D  128
#define PB_H  128
#define PB_ED 8

#define H2_STRIDE 132   // h2s stride: A-fragment reads conflict-free (g*4+tg)
#define WK_STRIDE 136   // weight-chunk stride: B-fragment reads conflict-free (tg*8+g)
#define XS_STRIDE 20    // X-chunk stride: A-fragment reads conflict-free (g*20 mod 32 spread)

// ---------------- scratch (device globals; no runtime allocation) ----------
__device__ float g_pooled[(size_t)PB_N1 * PB_H];  // 16.8 MB (reused at level 0)
__device__ float g_h1[(size_t)PB_N1 * PB_H];      // 16.8 MB
__device__ float g_Wc[3 * PB_D * PB_H];           // W_fe @ W_x[l][:128]
__device__ float g_bias[3 * PB_H];                // b_fe @ W_x[l][:128] + b_r[l]

// ---------------- tf32 / math helpers ---------------------------------------
__device__ __forceinline__ unsigned f2tf(float f) {
    unsigned r; asm("cvt.rna.tf32.f32 %0, %1;" : "=r"(r) : "f"(f)); return r;
}
__device__ __forceinline__ void mma8(float4& d, const unsigned a[4],
                                     unsigned b0, unsigned b1) {
    asm volatile(
        "mma.sync.aligned.m16n8k8.row.col.f32.tf32.tf32.f32 "
        "{%0,%1,%2,%3},{%4,%5,%6,%7},{%8,%9},{%0,%1,%2,%3};"
        : "+f"(d.x), "+f"(d.y), "+f"(d.z), "+f"(d.w)
        : "r"(a[0]), "r"(a[1]), "r"(a[2]), "r"(a[3]), "r"(b0), "r"(b1));
}
__device__ __forceinline__ float fast_tanh(float x) {
    float e = __expf(2.f * x);
    return 1.f - __fdividef(2.f, e + 1.f);
}

// store a prefetched X chunk (regs -> smem, tf32)
__device__ __forceinline__ void storeX(unsigned* Xb, int t,
                                       const float4& xa, const float4& xb) {
    int f = t, r = f >> 2, c4 = (f & 3) * 4;
    unsigned* d = Xb + r * XS_STRIDE + c4;
    d[0] = f2tf(xa.x); d[1] = f2tf(xa.y); d[2] = f2tf(xa.z); d[3] = f2tf(xa.w);
    f = t + 256; r = f >> 2; c4 = (f & 3) * 4;
    d = Xb + r * XS_STRIDE + c4;
    d[0] = f2tf(xb.x); d[1] = f2tf(xb.y); d[2] = f2tf(xb.z); d[3] = f2tf(xb.w);
}
__device__ __forceinline__ void storeW(unsigned* Wb, int t,
                                       const float4& wa, const float4& wb) {
    int f = t, r = f >> 5, c4 = (f & 31) * 4;
    unsigned* d = Wb + r * WK_STRIDE + c4;
    d[0] = f2tf(wa.x); d[1] = f2tf(wa.y); d[2] = f2tf(wa.z); d[3] = f2tf(wa.w);
    f = t + 256; r = f >> 5; c4 = (f & 31) * 4;
    d = Wb + r * WK_STRIDE + c4;
    d[0] = f2tf(wb.x); d[1] = f2tf(wb.y); d[2] = f2tf(wb.z); d[3] = f2tf(wb.w);
}
__device__ __forceinline__ void loadX(const float* A, size_t rowbase, int kb,
                                      int t, float4& xa, float4& xb) {
    int f = t, r = f >> 2, c4 = (f & 3) * 4;
    xa = *(const float4*)(A + (rowbase + r) * 128 + kb + c4);
    f = t + 256; r = f >> 2; c4 = (f & 3) * 4;
    xb = *(const float4*)(A + (rowbase + r) * 128 + kb + c4);
}
__device__ __forceinline__ void loadW(const float* W, int kb,
                                      int t, float4& wa, float4& wb) {
    int f = t, r = f >> 5, c4 = (f & 31) * 4;
    wa = *(const float4*)(W + (size_t)(kb + r) * 128 + c4);
    f = t + 256; r = f >> 5; c4 = (f & 31) * 4;
    wb = *(const float4*)(W + (size_t)(kb + r) * 128 + c4);
}

// one 16-K-deep mma step on a 128x128 tile (per-warp 64x32 sub-tile)
__device__ __forceinline__ void mma_chunk(float4 acc[4][4],
                                          const unsigned* Xb, int xstride,
                                          const unsigned* Wb,
                                          int warpM, int warpN, int g, int tg) {
    #pragma unroll
    for (int ks = 0; ks < 2; ++ks) {
        int k0 = ks * 8;
        unsigned a[4][4], b[4][2];
        #pragma unroll
        for (int i = 0; i < 4; ++i) {
            int rb = warpM * 64 + i * 16;
            a[i][0] = Xb[(rb + g) * xstride + k0 + tg];
            a[i][1] = Xb[(rb + g + 8) * xstride + k0 + tg];
            a[i][2] = Xb[(rb + g) * xstride + k0 + tg + 4];
            a[i][3] = Xb[(rb + g + 8) * xstride + k0 + tg + 4];
        }
        #pragma unroll
        for (int j = 0; j < 4; ++j) {
            int col = warpN * 32 + j * 8 + g;
            b[j][0] = Wb[(k0 + tg) * WK_STRIDE + col];
            b[j][1] = Wb[(k0 + tg + 4) * WK_STRIDE + col];
        }
        #pragma unroll
        for (int i = 0; i < 4; ++i)
            #pragma unroll
            for (int j = 0; j < 4; ++j) mma8(acc[i][j], a[i], b[j][0], b[j][1]);
    }
}

// ---------------- prep: Wc[l] = W_fe @ W_x[l][0:128,:] ---------------------
__global__ void prep_wc(const float* __restrict__ W_fe,
                        const float* __restrict__ W_x) {
    int l = blockIdx.x >> 7;
    int d = blockIdx.x & 127;
    int h = threadIdx.x;
    const float* wx = W_x + (size_t)l * 132 * 128;
    float acc = 0.f;
    #pragma unroll 8
    for (int k = 0; k < 128; ++k)
        acc += W_fe[d * 128 + k] * wx[k * 128 + h];
    g_Wc[((size_t)l * 128 + d) * 128 + h] = acc;
}

__global__ void prep_bias(const float* __restrict__ b_fe,
                          const float* __restrict__ W_x,
                          const float* __restrict__ b_r) {
    int l = blockIdx.x;
    int h = threadIdx.x;
    const float* wx = W_x + (size_t)l * 132 * 128;
    float acc = b_r[l * 128 + h];
    #pragma unroll 8
    for (int d = 0; d < 128; ++d)
        acc += b_fe[d] * wx[d * 128 + h];
    g_bias[l * 128 + h] = acc;
}

// ============================================================================
// fused_level: per block 128 child rows = 8 parents (warp w <-> parent w).
//   A: child_h = tanh(xin @ Wc + bias + typerow) -> smem tf32  (or load hin)
//   gates: each lane computes its 8 mma-A-fragment gate values in registers
//   C: M_p = G_p @ child_h_p per warp (writes back into h2s)
//   D: Hc = relu(M @ Wg + bg); 16-row maxpool -> pooled
// Single-sync double-buffered K pipeline on A and D.
// ============================================================================
__global__ void __launch_bounds__(256, 2)
fused_level(const float* __restrict__ xin, const int* __restrict__ tvec,
            const float* __restrict__ tapg, const float* __restrict__ Wc,
            const float* __restrict__ biasg,
            const float* __restrict__ hin,
            const float* __restrict__ Ag, const float* __restrict__ Eg,
            const float* __restrict__ Weg,
            const float* __restrict__ Wg, const float* __restrict__ bgg,
            float* __restrict__ pooled)
{
    extern __shared__ unsigned char smraw[];
    unsigned* h2s = (unsigned*)smraw;                       // [128][132]
    unsigned* Xs  = h2s + 128 * H2_STRIDE;                  // [2][128][20]
    unsigned* Wks = Xs + 2 * 128 * XS_STRIDE;               // [2][16][136]
    float* taps   = (float*)(Wks + 2 * 16 * WK_STRIDE);     // [4][128]
    float* bgs    = taps + 4 * 128;                         // [128]
    float* biass  = bgs + 128;                              // [128]
    int*   ts     = (int*)(biass + 128);                    // [128]

    const int t = threadIdx.x;
    const int lane = t & 31, wid = t >> 5;
    const int warpM = wid >> 2, warpN = wid & 3;
    const int g = lane >> 2, tg = lane & 3;
    const size_t rowbase = (size_t)blockIdx.x * 128;

    if (t < 128) bgs[t] = bgg[t];

    float4 acc[4][4];
    float gg[2][2][2];   // [c8][k8][k4] gate values for this lane's parent

    if (xin) {
        if (t < 128) { biass[t] = biasg[t]; ts[t] = tvec[rowbase + t]; }
        taps[t] = tapg[t]; taps[t + 256] = tapg[t + 256];

        #pragma unroll
        for (int i = 0; i < 4; ++i)
            #pragma unroll
            for (int j = 0; j < 4; ++j) acc[i][j] = make_float4(0.f, 0.f, 0.f, 0.f);

        float4 xa, xb, wa, wb;
        loadX(xin, rowbase, 0, t, xa, xb);
        loadW(Wc, 0, t, wa, wb);
        #pragma unroll
        for (int it = 0; it < 8; ++it) {
            unsigned* Xb = Xs + (it & 1) * 128 * XS_STRIDE;
            unsigned* Wb = Wks + (it & 1) * 16 * WK_STRIDE;
            storeX(Xb, t, xa, xb);
            storeW(Wb, t, wa, wb);
            __syncthreads();
            if (it < 7) {
                loadX(xin, rowbase, (it + 1) * 16, t, xa, xb);
                loadW(Wc, (it + 1) * 16, t, wa, wb);
            }
            mma_chunk(acc, Xb, XS_STRIDE, Wb, warpM, warpN, g, tg);
        }

        // gates (register-resident, loads overlap epilogue latency below)
        {
            const size_t ebase = (size_t)blockIdx.x * 2048 + wid * 256;
            float we0 = Weg[0], we1 = Weg[1], we2 = Weg[2], we3 = Weg[3];
            float we4 = Weg[4], we5 = Weg[5], we6 = Weg[6], we7 = Weg[7];
            #pragma unroll
            for (int c8 = 0; c8 < 2; ++c8)
                #pragma unroll
                for (int k8 = 0; k8 < 2; ++k8)
                    #pragma unroll
                    for (int k4 = 0; k4 < 2; ++k4) {
                        int c = g + 8 * c8, k = tg + 4 * k4 + 8 * k8;
                        const float* e = Eg + (ebase + c * 16 + k) * 8;
                        float4 e0 = *(const float4*)(e);
                        float4 e1 = *(const float4*)(e + 4);
                        float s = e0.x * we0 + e0.y * we1 + e0.z * we2 + e0.w * we3
                                + e1.x * we4 + e1.y * we5 + e1.z * we6 + e1.w * we7;
                        gg[c8][k8][k4] = Ag[ebase + c * 16 + k] / (1.f + __expf(-s));
                    }
        }

        // epilogue: fast tanh -> h2s (tf32 bits)
        #pragma unroll
        for (int i = 0; i < 4; ++i) {
            int r0 = warpM * 64 + i * 16 + g, r1 = r0 + 8;
            const float* tap0 = taps + ts[r0] * 128;
            const float* tap1 = taps + ts[r1] * 128;
            #pragma unroll
            for (int j = 0; j < 4; ++j) {
                int c0 = warpN * 32 + j * 8 + tg * 2;
                h2s[r0 * H2_STRIDE + c0]     = f2tf(fast_tanh(acc[i][j].x + biass[c0]     + tap0[c0]));
                h2s[r0 * H2_STRIDE + c0 + 1] = f2tf(fast_tanh(acc[i][j].y + biass[c0 + 1] + tap0[c0 + 1]));
                h2s[r1 * H2_STRIDE + c0]     = f2tf(fast_tanh(acc[i][j].z + biass[c0]     + tap1[c0]));
                h2s[r1 * H2_STRIDE + c0 + 1] = f2tf(fast_tanh(acc[i][j].w + biass[c0 + 1] + tap1[c0 + 1]));
            }
        }
    } else {
        // load child hidden tile from global
        #pragma unroll
        for (int u = 0; u < 16; ++u) {
            int f = t + u * 256; int r = f >> 5, c4 = (f & 31) * 4;
            float4 v = *(const float4*)(hin + (rowbase + r) * 128 + c4);
            unsigned* d = h2s + r * H2_STRIDE + c4;
            d[0] = f2tf(v.x); d[1] = f2tf(v.y); d[2] = f2tf(v.z); d[3] = f2tf(v.w);
        }
        {
            const size_t ebase = (size_t)blockIdx.x * 2048 + wid * 256;
            float we0 = Weg[0], we1 = Weg[1], we2 = Weg[2], we3 = Weg[3];
            float we4 = Weg[4], we5 = Weg[5], we6 = Weg[6], we7 = Weg[7];
            #pragma unroll
            for (int c8 = 0; c8 < 2; ++c8)
                #pragma unroll
                for (int k8 = 0; k8 < 2; ++k8)
                    #pragma unroll
                    for (int k4 = 0; k4 < 2; ++k4) {
                        int c = g + 8 * c8, k = tg + 4 * k4 + 8 * k8;
                        const float* e = Eg + (ebase + c * 16 + k) * 8;
                        float4 e0 = *(const float4*)(e);
                        float4 e1 = *(const float4*)(e + 4);
                        float s = e0.x * we0 + e0.y * we1 + e0.z * we2 + e0.w * we3
                                + e1.x * we4 + e1.y * we5 + e1.z * we6 + e1.w * we7;
                        gg[c8][k8][k4] = Ag[ebase + c * 16 + k] / (1.f + __expf(-s));
                    }
        }
    }
    __syncthreads();   // h2s complete, all warps may read any parent rows

    // Phase C: per-parent mix M_p = G_p @ child_h_p  (warp wid = parent)
    {
        float4 macc[16];
        #pragma unroll
        for (int j = 0; j < 16; ++j) macc[j] = make_float4(0.f, 0.f, 0.f, 0.f);
        int p = wid;
        #pragma unroll
        for (int ks = 0; ks < 2; ++ks) {
            unsigned a[4];
            a[0] = f2tf(gg[0][ks][0]);
            a[1] = f2tf(gg[1][ks][0]);
            a[2] = f2tf(gg[0][ks][1]);
            a[3] = f2tf(gg[1][ks][1]);
            #pragma unroll
            for (int j = 0; j < 16; ++j) {
                unsigned b0 = h2s[(p * 16 + ks * 8 + tg) * H2_STRIDE + j * 8 + g];
                unsigned b1 = h2s[(p * 16 + ks * 8 + tg + 4) * H2_STRIDE + j * 8 + g];
                mma8(macc[j], a, b0, b1);
            }
        }
        __syncwarp();
        #pragma unroll
        for (int j = 0; j < 16; ++j) {
            int c0 = j * 8 + tg * 2;
            h2s[(p * 16 + g) * H2_STRIDE + c0]         = f2tf(macc[j].x);
            h2s[(p * 16 + g) * H2_STRIDE + c0 + 1]     = f2tf(macc[j].y);
            h2s[(p * 16 + g + 8) * H2_STRIDE + c0]     = f2tf(macc[j].z);
            h2s[(p * 16 + g + 8) * H2_STRIDE + c0 + 1] = f2tf(macc[j].w);
        }
    }
    __syncthreads();

    // Phase D: Hc = relu(M @ Wg + bg); maxpool over each parent's 16 rows
    #pragma unroll
    for (int i = 0; i < 4; ++i)
        #pragma unroll
        for (int j = 0; j < 4; ++j) acc[i][j] = make_float4(0.f, 0.f, 0.f, 0.f);

    {
        float4 wa, wb;
        loadW(Wg, 0, t, wa, wb);
        #pragma unroll
        for (int it = 0; it < 8; ++it) {
            unsigned* Wb = Wks + (it & 1) * 16 * WK_STRIDE;
            storeW(Wb, t, wa, wb);
            __syncthreads();
            if (it < 7) loadW(Wg, (it + 1) * 16, t, wa, wb);
            #pragma unroll
            for (int ks = 0; ks < 2; ++ks) {
                int k0 = it * 16 + ks * 8;
                unsigned a[4][4], b[4][2];
                #pragma unroll
                for (int i = 0; i < 4; ++i) {
                    int rb = warpM * 64 + i * 16;
                    a[i][0] = h2s[(rb + g) * H2_STRIDE + k0 + tg];
                    a[i][1] = h2s[(rb + g + 8) * H2_STRIDE + k0 + tg];
                    a[i][2] = h2s[(rb + g) * H2_STRIDE + k0 + tg + 4];
                    a[i][3] = h2s[(rb + g + 8) * H2_STRIDE + k0 + tg + 4];
                }
                #pragma unroll
                for (int j = 0; j < 4; ++j) {
                    int col = warpN * 32 + j * 8 + g;
                    b[j][0] = Wb[(ks * 8 + tg) * WK_STRIDE + col];
                    b[j][1] = Wb[(ks * 8 + tg + 4) * WK_STRIDE + col];
                }
                #pragma unroll
                for (int i = 0; i < 4; ++i)
                    #pragma unroll
                    for (int j = 0; j < 4; ++j) mma8(acc[i][j], a[i], b[j][0], b[j][1]);
            }
        }
    }

    // relu + 16-row maxpool (m-tile i == parent warpM*4+i exactly)
    #pragma unroll
    for (int i = 0; i < 4; ++i) {
        size_t parent = (size_t)blockIdx.x * 8 + warpM * 4 + i;
        #pragma unroll
        for (int j = 0; j < 4; ++j) {
            int c0 = warpN * 32 + j * 8 + tg * 2;
            float b0 = bgs[c0], b1 = bgs[c0 + 1];
            float v0 = fmaxf(fmaxf(acc[i][j].x + b0, acc[i][j].z + b0), 0.f);
            float v1 = fmaxf(fmaxf(acc[i][j].y + b1, acc[i][j].w + b1), 0.f);
            #pragma unroll
            for (int off = 16; off >= 4; off >>= 1) {
                v0 = fmaxf(v0, __shfl_xor_sync(0xffffffffu, v0, off));
                v1 = fmaxf(v1, __shfl_xor_sync(0xffffffffu, v1, off));
            }
            if (lane < 4)
                *(float2*)(pooled + parent * 128 + c0) = make_float2(v0, v1);
        }
    }
}

// ============================================================================
// gemm_tanh: out = tanh(A0 @ W0 + A1 @ W1 + bias + typerow[t]) , tf32 mma
// Single-sync double-buffered 16-chunk pipeline (2 segments x 8 chunks).
// ============================================================================
__global__ void __launch_bounds__(256, 2)
gemm_tanh(const float* __restrict__ A0g, const float* __restrict__ W0,
          const float* __restrict__ A1g, const float* __restrict__ W1,
          const float* __restrict__ biasg, const float* __restrict__ tapg,
          const int* __restrict__ tvec, float* __restrict__ out)
{
    __shared__ unsigned Xs[2][128 * XS_STRIDE];
    __shared__ unsigned Wks[2][16 * WK_STRIDE];
    __shared__ float taps[4][128];
    __shared__ float biass[128];
    __shared__ int ts[128];

    const int t = threadIdx.x;
    const int lane = t & 31, wid = t >> 5;
    const int warpM = wid >> 2, warpN = wid & 3;
    const int g = lane >> 2, tg = lane & 3;
    const size_t rowbase = (size_t)blockIdx.x * 128;

    if (t < 128) { biass[t] = biasg[t]; ts[t] = tvec[rowbase + t]; }
    ((float*)taps)[t] = tapg[t]; ((float*)taps)[t + 256] = tapg[t + 256];

    const float* Aseg[2] = {A0g, A1g};
    const float* Wseg[2] = {W0, W1};

    float4 acc[4][4];
    #pragma unroll
    for (int i = 0; i < 4; ++i)
        #pragma unroll
        for (int j = 0; j < 4; ++j) acc[i][j] = make_float4(0.f, 0.f, 0.f, 0.f);

    float4 xa, xb, wa, wb;
    loadX(A0g, rowbase, 0, t, xa, xb);
    loadW(W0, 0, t, wa, wb);
    #pragma unroll
    for (int it = 0; it < 16; ++it) {
        unsigned* Xb = Xs[it & 1];
        unsigned* Wb = Wks[it & 1];
        storeX(Xb, t, xa, xb);
        storeW(Wb, t, wa, wb);
        __syncthreads();
        if (it < 15) {
            int nit = it + 1;
            loadX(Aseg[nit >> 3], rowbase, (nit & 7) * 16, t, xa, xb);
            loadW(Wseg[nit >> 3], (nit & 7) * 16, t, wa, wb);
        }
        mma_chunk(acc, Xb, XS_STRIDE, Wb, warpM, warpN, g, tg);
    }

    #pragma unroll
    for (int i = 0; i < 4; ++i) {
        int r0 = warpM * 64 + i * 16 + g, r1 = r0 + 8;
        const float* tap0 = taps[ts[r0]];
        const float* tap1 = taps[ts[r1]];
        #pragma unroll
        for (int j = 0; j < 4; ++j) {
            int c0 = warpN * 32 + j * 8 + tg * 2;
            float o0 = fast_tanh(acc[i][j].x + biass[c0]     + tap0[c0]);
            float o1 = fast_tanh(acc[i][j].y + biass[c0 + 1] + tap0[c0 + 1]);
            float o2 = fast_tanh(acc[i][j].z + biass[c0]     + tap1[c0]);
            float o3 = fast_tanh(acc[i][j].w + biass[c0 + 1] + tap1[c0 + 1]);
            *(float2*)(out + (rowbase + r0) * 128 + c0) = make_float2(o0, o1);
            *(float2*)(out + (rowbase + r1) * 128 + c0) = make_float2(o2, o3);
        }
    }
}

// ---------------- launch -----------------------------------------------
extern "C" void kernel_launch(void* const* d_in, const int* in_sizes, int n_in,
                              void* d_out, int out_size) {
    const float* x0   = (const float*)d_in[0];
    const float* x1   = (const float*)d_in[1];
    const float* x2   = (const float*)d_in[2];
    const int*   t0   = (const int*)  d_in[3];
    const int*   t1   = (const int*)  d_in[4];
    const int*   t2   = (const int*)  d_in[5];
    const float* A0   = (const float*)d_in[6];
    const float* A1   = (const float*)d_in[7];
    const float* E0   = (const float*)d_in[8];
    const float* E1   = (const float*)d_in[9];
    const float* W_fe = (const float*)d_in[10];
    const float* b_fe = (const float*)d_in[11];
    const float* W_x  = (const float*)d_in[12];
    const float* W_h  = (const float*)d_in[13];
    const float* W_e  = (const float*)d_in[14];
    const float* W_g  = (const float*)d_in[15];
    const float* b_g  = (const float*)d_in[16];
    const float* b_r  = (const float*)d_in[17];

    float *pooled, *h1, *Wc, *bias;
    cudaGetSymbolAddress((void**)&pooled, g_pooled);
    cudaGetSymbolAddress((void**)&h1,     g_h1);
    cudaGetSymbolAddress((void**)&Wc,     g_Wc);
    cudaGetSymbolAddress((void**)&bias,   g_bias);

    const int SMEMSZ = (128 * H2_STRIDE + 2 * 128 * XS_STRIDE + 2 * 16 * WK_STRIDE) * 4
                     + (4 * 128 + 128 + 128 + 128) * 4;   // 109,056 B (2 CTAs/SM)
    cudaFuncSetAttribute(fused_level, cudaFuncAttributeMaxDynamicSharedMemorySize, SMEMSZ);

    // fold W_fe/b_fe into per-level weights
    prep_wc<<<3 * 128, 128>>>(W_fe, W_x);
    prep_bias<<<3, 128>>>(b_fe, W_x, b_r);

    // level 2 + level 1 GNN fused: x2 -> h2 (smem) -> gate/mix -> relu GEMM -> pooled1
    fused_level<<<PB_N2 / 128, 256, SMEMSZ>>>(
        x2, t2, W_x + 2 * 132 * 128 + 128 * 128, Wc + 2 * 128 * 128, bias + 2 * 128,
        nullptr, A1, E1, W_e + 8, W_g + 128 * 128, b_g + 128, pooled);

    // h1 = tanh(x1 @ Wc1 + pooled1 @ W_h1 + bias1 + typerow)
    gemm_tanh<<<PB_N1 / 128, 256>>>(
        x1, Wc + 128 * 128, pooled, W_h + 128 * 128,
        bias + 128, W_x + 132 * 128 + 128 * 128, t1, h1);

    // level 0 GNN fused (child hidden loaded from h1)
    fused_level<<<PB_N1 / 128, 256, SMEMSZ>>>(
        nullptr, nullptr, nullptr, nullptr, nullptr,
        h1, A0, E0, W_e, W_g, b_g, pooled);

    // roots: h0 -> d_out
    gemm_tanh<<<PB_N0 / 128, 256>>>(
        x0, Wc, pooled, W_h,
        bias, W_x + 128 * 128, t0, (float*)d_out);
}

// round 9
// speedup vs baseline: 2.2779x; 1.0133x over previous
#include <cuda_runtime.h>
#include <math.h>

// Problem constants
#define PB_N0 2048
#define PB_N1 32768
#define PB_N2 524288
#define PB_C  16
#define PB_D  128
#define PB_H  128
#define PB_ED 8

#define H2_STRIDE 132   // h2s stride: A-fragment reads conflict-free (g*4+tg)
#define WK_STRIDE 136   // weight-chunk stride: B-fragment reads conflict-free (tg*8+g)
#define XS_STRIDE 20    // X-chunk stride: A-fragment reads conflict-free

// ---------------- scratch (device globals; no runtime allocation) ----------
__device__ float    g_pooled[(size_t)PB_N1 * PB_H];  // 16.8 MB (reused at level 0)
__device__ float    g_h1[(size_t)PB_N1 * PB_H];      // 16.8 MB
__device__ unsigned g_Wc[3 * PB_D * PB_H];           // tf32 bits: W_fe @ W_x[l][:128]
__device__ unsigned g_Whc[2 * PB_H * PB_H];          // tf32 bits: W_h levels 0,1
__device__ unsigned g_Wgc[2 * PB_H * PB_H];          // tf32 bits: W_g levels 0,1
__device__ float    g_bias[3 * PB_H];                // b_fe @ W_x[l][:128] + b_r[l]

// ---------------- tf32 / math helpers ---------------------------------------
__device__ __forceinline__ unsigned f2tf(float f) {
    unsigned r; asm("cvt.rna.tf32.f32 %0, %1;" : "=r"(r) : "f"(f)); return r;
}
__device__ __forceinline__ void mma8(float4& d, const unsigned a[4],
                                     unsigned b0, unsigned b1) {
    asm volatile(
        "mma.sync.aligned.m16n8k8.row.col.f32.tf32.tf32.f32 "
        "{%0,%1,%2,%3},{%4,%5,%6,%7},{%8,%9},{%0,%1,%2,%3};"
        : "+f"(d.x), "+f"(d.y), "+f"(d.z), "+f"(d.w)
        : "r"(a[0]), "r"(a[1]), "r"(a[2]), "r"(a[3]), "r"(b0), "r"(b1));
}
__device__ __forceinline__ float fast_tanh(float x) {
    float e = __expf(2.f * x);
    return 1.f - __fdividef(2.f, e + 1.f);
}

// ---------------- staging: X (fp32 -> cvt -> STS.128), W (tf32 bits, raw) ---
__device__ __forceinline__ void loadX(const float* A, size_t rowbase, int kb,
                                      int t, float4& xa, float4& xb) {
    int f = t, r = f >> 2, c4 = (f & 3) * 4;
    xa = *(const float4*)(A + (rowbase + r) * 128 + kb + c4);
    f = t + 256; r = f >> 2; c4 = (f & 3) * 4;
    xb = *(const float4*)(A + (rowbase + r) * 128 + kb + c4);
}
__device__ __forceinline__ void storeX(unsigned* Xb, int t,
                                       const float4& xa, const float4& xb) {
    int f = t, r = f >> 2, c4 = (f & 3) * 4;
    uint4 v;
    v.x = f2tf(xa.x); v.y = f2tf(xa.y); v.z = f2tf(xa.z); v.w = f2tf(xa.w);
    *(uint4*)(Xb + r * XS_STRIDE + c4) = v;
    f = t + 256; r = f >> 2; c4 = (f & 3) * 4;
    v.x = f2tf(xb.x); v.y = f2tf(xb.y); v.z = f2tf(xb.z); v.w = f2tf(xb.w);
    *(uint4*)(Xb + r * XS_STRIDE + c4) = v;
}
__device__ __forceinline__ void loadWc(const unsigned* W, int kb,
                                       int t, uint4& wa, uint4& wb) {
    int f = t, r = f >> 5, c4 = (f & 31) * 4;
    wa = *(const uint4*)(W + (size_t)(kb + r) * 128 + c4);
    f = t + 256; r = f >> 5; c4 = (f & 31) * 4;
    wb = *(const uint4*)(W + (size_t)(kb + r) * 128 + c4);
}
__device__ __forceinline__ void storeWc(unsigned* Wb, int t,
                                        const uint4& wa, const uint4& wb) {
    int f = t, r = f >> 5, c4 = (f & 31) * 4;
    *(uint4*)(Wb + r * WK_STRIDE + c4) = wa;
    f = t + 256; r = f >> 5; c4 = (f & 31) * 4;
    *(uint4*)(Wb + r * WK_STRIDE + c4) = wb;
}

// one 16-K-deep mma step on a 128x128 tile (per-warp 64x32 sub-tile)
__device__ __forceinline__ void mma_chunk(float4 acc[4][4],
                                          const unsigned* Xb, int xstride,
                                          const unsigned* Wb,
                                          int warpM, int warpN, int g, int tg) {
    #pragma unroll
    for (int ks = 0; ks < 2; ++ks) {
        int k0 = ks * 8;
        unsigned a[4][4], b[4][2];
        #pragma unroll
        for (int i = 0; i < 4; ++i) {
            int rb = warpM * 64 + i * 16;
            a[i][0] = Xb[(rb + g) * xstride + k0 + tg];
            a[i][1] = Xb[(rb + g + 8) * xstride + k0 + tg];
            a[i][2] = Xb[(rb + g) * xstride + k0 + tg + 4];
            a[i][3] = Xb[(rb + g + 8) * xstride + k0 + tg + 4];
        }
        #pragma unroll
        for (int j = 0; j < 4; ++j) {
            int col = warpN * 32 + j * 8 + g;
            b[j][0] = Wb[(k0 + tg) * WK_STRIDE + col];
            b[j][1] = Wb[(k0 + tg + 4) * WK_STRIDE + col];
        }
        #pragma unroll
        for (int i = 0; i < 4; ++i)
            #pragma unroll
            for (int j = 0; j < 4; ++j) mma8(acc[i][j], a[i], b[j][0], b[j][1]);
    }
}

// ---------------- prep: Wc[l] = tf32(W_fe @ W_x[l][0:128,:]) ----------------
__global__ void prep_wc(const float* __restrict__ W_fe,
                        const float* __restrict__ W_x) {
    int l = blockIdx.x >> 7;
    int d = blockIdx.x & 127;
    int h = threadIdx.x;
    const float* wx = W_x + (size_t)l * 132 * 128;
    float acc = 0.f;
    #pragma unroll 8
    for (int k = 0; k < 128; ++k)
        acc += W_fe[d * 128 + k] * wx[k * 128 + h];
    g_Wc[((size_t)l * 128 + d) * 128 + h] = f2tf(acc);
}

__global__ void prep_bias(const float* __restrict__ b_fe,
                          const float* __restrict__ W_x,
                          const float* __restrict__ b_r) {
    int l = blockIdx.x;
    int h = threadIdx.x;
    const float* wx = W_x + (size_t)l * 132 * 128;
    float acc = b_r[l * 128 + h];
    #pragma unroll 8
    for (int d = 0; d < 128; ++d)
        acc += b_fe[d] * wx[d * 128 + h];
    g_bias[l * 128 + h] = acc;
}

// convert W_h / W_g levels 0,1 to tf32 bits
__global__ void prep_cvt(const float* __restrict__ Wh,
                         const float* __restrict__ Wg) {
    int i = blockIdx.x * 256 + threadIdx.x;   // 0 .. 32767
    g_Whc[i] = f2tf(Wh[i]);
    g_Wgc[i] = f2tf(Wg[i]);
}

// ============================================================================
// fused_level: per block 128 child rows = 8 parents (warp w <-> parent w).
// ============================================================================
__global__ void __launch_bounds__(256, 2)
fused_level(const float* __restrict__ xin, const int* __restrict__ tvec,
            const float* __restrict__ tapg, const unsigned* __restrict__ Wc,
            const float* __restrict__ biasg,
            const float* __restrict__ hin,
            const float* __restrict__ Ag, const float* __restrict__ Eg,
            const float* __restrict__ Weg,
            const unsigned* __restrict__ Wg, const float* __restrict__ bgg,
            float* __restrict__ pooled)
{
    extern __shared__ unsigned char smraw[];
    unsigned* h2s = (unsigned*)smraw;                       // [128][132]
    unsigned* Xs  = h2s + 128 * H2_STRIDE;                  // [2][128][20]
    unsigned* Wks = Xs + 2 * 128 * XS_STRIDE;               // [2][16][136]
    float* taps   = (float*)(Wks + 2 * 16 * WK_STRIDE);     // [4][128]
    float* bgs    = taps + 4 * 128;                         // [128]
    float* biass  = bgs + 128;                              // [128]
    int*   ts     = (int*)(biass + 128);                    // [128]

    const int t = threadIdx.x;
    const int lane = t & 31, wid = t >> 5;
    const int warpM = wid >> 2, warpN = wid & 3;
    const int g = lane >> 2, tg = lane & 3;
    const size_t rowbase = (size_t)blockIdx.x * 128;

    if (t < 128) bgs[t] = bgg[t];

    float4 acc[4][4];
    float gg[2][2][2];   // [c8][k8][k4] gate values for this lane's parent

    if (xin) {
        if (t < 128) { biass[t] = biasg[t]; ts[t] = tvec[rowbase + t]; }
        taps[t] = tapg[t]; taps[t + 256] = tapg[t + 256];

        #pragma unroll
        for (int i = 0; i < 4; ++i)
            #pragma unroll
            for (int j = 0; j < 4; ++j) acc[i][j] = make_float4(0.f, 0.f, 0.f, 0.f);

        float4 xa, xb; uint4 wa, wb;
        loadX(xin, rowbase, 0, t, xa, xb);
        loadWc(Wc, 0, t, wa, wb);
        #pragma unroll
        for (int it = 0; it < 8; ++it) {
            unsigned* Xb = Xs + (it & 1) * 128 * XS_STRIDE;
            unsigned* Wb = Wks + (it & 1) * 16 * WK_STRIDE;
            storeX(Xb, t, xa, xb);
            storeWc(Wb, t, wa, wb);
            __syncthreads();
            if (it < 7) {
                loadX(xin, rowbase, (it + 1) * 16, t, xa, xb);
                loadWc(Wc, (it + 1) * 16, t, wa, wb);
            }
            mma_chunk(acc, Xb, XS_STRIDE, Wb, warpM, warpN, g, tg);
        }

        // gates (register-resident, loads overlap epilogue latency below)
        {
            const size_t ebase = (size_t)blockIdx.x * 2048 + wid * 256;
            float we0 = Weg[0], we1 = Weg[1], we2 = Weg[2], we3 = Weg[3];
            float we4 = Weg[4], we5 = Weg[5], we6 = Weg[6], we7 = Weg[7];
            #pragma unroll
            for (int c8 = 0; c8 < 2; ++c8)
                #pragma unroll
                for (int k8 = 0; k8 < 2; ++k8)
                    #pragma unroll
                    for (int k4 = 0; k4 < 2; ++k4) {
                        int c = g + 8 * c8, k = tg + 4 * k4 + 8 * k8;
                        const float* e = Eg + (ebase + c * 16 + k) * 8;
                        float4 e0 = *(const float4*)(e);
                        float4 e1 = *(const float4*)(e + 4);
                        float s = e0.x * we0 + e0.y * we1 + e0.z * we2 + e0.w * we3
                                + e1.x * we4 + e1.y * we5 + e1.z * we6 + e1.w * we7;
                        gg[c8][k8][k4] = Ag[ebase + c * 16 + k] / (1.f + __expf(-s));
                    }
        }

        // epilogue: fast tanh -> h2s (tf32 bits)
        #pragma unroll
        for (int i = 0; i < 4; ++i) {
            int r0 = warpM * 64 + i * 16 + g, r1 = r0 + 8;
            const float* tap0 = taps + ts[r0] * 128;
            const float* tap1 = taps + ts[r1] * 128;
            #pragma unroll
            for (int j = 0; j < 4; ++j) {
                int c0 = warpN * 32 + j * 8 + tg * 2;
                h2s[r0 * H2_STRIDE + c0]     = f2tf(fast_tanh(acc[i][j].x + biass[c0]     + tap0[c0]));
                h2s[r0 * H2_STRIDE + c0 + 1] = f2tf(fast_tanh(acc[i][j].y + biass[c0 + 1] + tap0[c0 + 1]));
                h2s[r1 * H2_STRIDE + c0]     = f2tf(fast_tanh(acc[i][j].z + biass[c0]     + tap1[c0]));
                h2s[r1 * H2_STRIDE + c0 + 1] = f2tf(fast_tanh(acc[i][j].w + biass[c0 + 1] + tap1[c0 + 1]));
            }
        }
    } else {
        // load child hidden tile from global (cvt + STS.128)
        #pragma unroll
        for (int u = 0; u < 16; ++u) {
            int f = t + u * 256; int r = f >> 5, c4 = (f & 31) * 4;
            float4 v = *(const float4*)(hin + (rowbase + r) * 128 + c4);
            uint4 w;
            w.x = f2tf(v.x); w.y = f2tf(v.y); w.z = f2tf(v.z); w.w = f2tf(v.w);
            *(uint4*)(h2s + r * H2_STRIDE + c4) = w;
        }
        {
            const size_t ebase = (size_t)blockIdx.x * 2048 + wid * 256;
            float we0 = Weg[0], we1 = Weg[1], we2 = Weg[2], we3 = Weg[3];
            float we4 = Weg[4], we5 = Weg[5], we6 = Weg[6], we7 = Weg[7];
            #pragma unroll
            for (int c8 = 0; c8 < 2; ++c8)
                #pragma unroll
                for (int k8 = 0; k8 < 2; ++k8)
                    #pragma unroll
                    for (int k4 = 0; k4 < 2; ++k4) {
                        int c = g + 8 * c8, k = tg + 4 * k4 + 8 * k8;
                        const float* e = Eg + (ebase + c * 16 + k) * 8;
                        float4 e0 = *(const float4*)(e);
                        float4 e1 = *(const float4*)(e + 4);
                        float s = e0.x * we0 + e0.y * we1 + e0.z * we2 + e0.w * we3
                                + e1.x * we4 + e1.y * we5 + e1.z * we6 + e1.w * we7;
                        gg[c8][k8][k4] = Ag[ebase + c * 16 + k] / (1.f + __expf(-s));
                    }
        }
    }
    __syncthreads();   // h2s complete, all warps may read any parent rows

    // Phase C: per-parent mix M_p = G_p @ child_h_p  (warp wid = parent)
    {
        float4 macc[16];
        #pragma unroll
        for (int j = 0; j < 16; ++j) macc[j] = make_float4(0.f, 0.f, 0.f, 0.f);
        int p = wid;
        #pragma unroll
        for (int ks = 0; ks < 2; ++ks) {
            unsigned a[4];
            a[0] = f2tf(gg[0][ks][0]);
            a[1] = f2tf(gg[1][ks][0]);
            a[2] = f2tf(gg[0][ks][1]);
            a[3] = f2tf(gg[1][ks][1]);
            #pragma unroll
            for (int j = 0; j < 16; ++j) {
                unsigned b0 = h2s[(p * 16 + ks * 8 + tg) * H2_STRIDE + j * 8 + g];
                unsigned b1 = h2s[(p * 16 + ks * 8 + tg + 4) * H2_STRIDE + j * 8 + g];
                mma8(macc[j], a, b0, b1);
            }
        }
        __syncwarp();
        #pragma unroll
        for (int j = 0; j < 16; ++j) {
            int c0 = j * 8 + tg * 2;
            h2s[(p * 16 + g) * H2_STRIDE + c0]         = f2tf(macc[j].x);
            h2s[(p * 16 + g) * H2_STRIDE + c0 + 1]     = f2tf(macc[j].y);
            h2s[(p * 16 + g + 8) * H2_STRIDE + c0]     = f2tf(macc[j].z);
            h2s[(p * 16 + g + 8) * H2_STRIDE + c0 + 1] = f2tf(macc[j].w);
        }
    }
    __syncthreads();

    // Phase D: Hc = relu(M @ Wg + bg); maxpool over each parent's 16 rows
    #pragma unroll
    for (int i = 0; i < 4; ++i)
        #pragma unroll
        for (int j = 0; j < 4; ++j) acc[i][j] = make_float4(0.f, 0.f, 0.f, 0.f);

    {
        uint4 wa, wb;
        loadWc(Wg, 0, t, wa, wb);
        #pragma unroll
        for (int it = 0; it < 8; ++it) {
            unsigned* Wb = Wks + (it & 1) * 16 * WK_STRIDE;
            storeWc(Wb, t, wa, wb);
            __syncthreads();
            if (it < 7) loadWc(Wg, (it + 1) * 16, t, wa, wb);
            #pragma unroll
            for (int ks = 0; ks < 2; ++ks) {
                int k0 = it * 16 + ks * 8;
                unsigned a[4][4], b[4][2];
                #pragma unroll
                for (int i = 0; i < 4; ++i) {
                    int rb = warpM * 64 + i * 16;
                    a[i][0] = h2s[(rb + g) * H2_STRIDE + k0 + tg];
                    a[i][1] = h2s[(rb + g + 8) * H2_STRIDE + k0 + tg];
                    a[i][2] = h2s[(rb + g) * H2_STRIDE + k0 + tg + 4];
                    a[i][3] = h2s[(rb + g + 8) * H2_STRIDE + k0 + tg + 4];
                }
                #pragma unroll
                for (int j = 0; j < 4; ++j) {
                    int col = warpN * 32 + j * 8 + g;
                    b[j][0] = Wb[(ks * 8 + tg) * WK_STRIDE + col];
                    b[j][1] = Wb[(ks * 8 + tg + 4) * WK_STRIDE + col];
                }
                #pragma unroll
                for (int i = 0; i < 4; ++i)
                    #pragma unroll
                    for (int j = 0; j < 4; ++j) mma8(acc[i][j], a[i], b[j][0], b[j][1]);
            }
        }
    }

    // relu + 16-row maxpool (m-tile i == parent warpM*4+i exactly)
    #pragma unroll
    for (int i = 0; i < 4; ++i) {
        size_t parent = (size_t)blockIdx.x * 8 + warpM * 4 + i;
        #pragma unroll
        for (int j = 0; j < 4; ++j) {
            int c0 = warpN * 32 + j * 8 + tg * 2;
            float b0 = bgs[c0], b1 = bgs[c0 + 1];
            float v0 = fmaxf(fmaxf(acc[i][j].x + b0, acc[i][j].z + b0), 0.f);
            float v1 = fmaxf(fmaxf(acc[i][j].y + b1, acc[i][j].w + b1), 0.f);
            #pragma unroll
            for (int off = 16; off >= 4; off >>= 1) {
                v0 = fmaxf(v0, __shfl_xor_sync(0xffffffffu, v0, off));
                v1 = fmaxf(v1, __shfl_xor_sync(0xffffffffu, v1, off));
            }
            if (lane < 4)
                *(float2*)(pooled + parent * 128 + c0) = make_float2(v0, v1);
        }
    }
}

// ============================================================================
// gemm_tanh: out = tanh(A0 @ W0 + A1 @ W1 + bias + typerow[t]) , tf32 mma
// W0/W1 are pre-converted tf32 bits.
// ============================================================================
__global__ void __launch_bounds__(256, 2)
gemm_tanh(const float* __restrict__ A0g, const unsigned* __restrict__ W0,
          const float* __restrict__ A1g, const unsigned* __restrict__ W1,
          const float* __restrict__ biasg, const float* __restrict__ tapg,
          const int* __restrict__ tvec, float* __restrict__ out)
{
    __shared__ unsigned Xs[2][128 * XS_STRIDE];
    __shared__ unsigned Wks[2][16 * WK_STRIDE];
    __shared__ float taps[4][128];
    __shared__ float biass[128];
    __shared__ int ts[128];

    const int t = threadIdx.x;
    const int lane = t & 31, wid = t >> 5;
    const int warpM = wid >> 2, warpN = wid & 3;
    const int g = lane >> 2, tg = lane & 3;
    const size_t rowbase = (size_t)blockIdx.x * 128;

    if (t < 128) { biass[t] = biasg[t]; ts[t] = tvec[rowbase + t]; }
    ((float*)taps)[t] = tapg[t]; ((float*)taps)[t + 256] = tapg[t + 256];

    const float* Aseg[2] = {A0g, A1g};
    const unsigned* Wseg[2] = {W0, W1};

    float4 acc[4][4];
    #pragma unroll
    for (int i = 0; i < 4; ++i)
        #pragma unroll
        for (int j = 0; j < 4; ++j) acc[i][j] = make_float4(0.f, 0.f, 0.f, 0.f);

    float4 xa, xb; uint4 wa, wb;
    loadX(A0g, rowbase, 0, t, xa, xb);
    loadWc(W0, 0, t, wa, wb);
    #pragma unroll
    for (int it = 0; it < 16; ++it) {
        unsigned* Xb = Xs[it & 1];
        unsigned* Wb = Wks[it & 1];
        storeX(Xb, t, xa, xb);
        storeWc(Wb, t, wa, wb);
        __syncthreads();
        if (it < 15) {
            int nit = it + 1;
            loadX(Aseg[nit >> 3], rowbase, (nit & 7) * 16, t, xa, xb);
            loadWc(Wseg[nit >> 3], (nit & 7) * 16, t, wa, wb);
        }
        mma_chunk(acc, Xb, XS_STRIDE, Wb, warpM, warpN, g, tg);
    }

    #pragma unroll
    for (int i = 0; i < 4; ++i) {
        int r0 = warpM * 64 + i * 16 + g, r1 = r0 + 8;
        const float* tap0 = taps[ts[r0]];
        const float* tap1 = taps[ts[r1]];
        #pragma unroll
        for (int j = 0; j < 4; ++j) {
            int c0 = warpN * 32 + j * 8 + tg * 2;
            float o0 = fast_tanh(acc[i][j].x + biass[c0]     + tap0[c0]);
            float o1 = fast_tanh(acc[i][j].y + biass[c0 + 1] + tap0[c0 + 1]);
            float o2 = fast_tanh(acc[i][j].z + biass[c0]     + tap1[c0]);
            float o3 = fast_tanh(acc[i][j].w + biass[c0 + 1] + tap1[c0 + 1]);
            *(float2*)(out + (rowbase + r0) * 128 + c0) = make_float2(o0, o1);
            *(float2*)(out + (rowbase + r1) * 128 + c0) = make_float2(o2, o3);
        }
    }
}

// ---------------- launch -----------------------------------------------
extern "C" void kernel_launch(void* const* d_in, const int* in_sizes, int n_in,
                              void* d_out, int out_size) {
    const float* x0   = (const float*)d_in[0];
    const float* x1   = (const float*)d_in[1];
    const float* x2   = (const float*)d_in[2];
    const int*   t0   = (const int*)  d_in[3];
    const int*   t1   = (const int*)  d_in[4];
    const int*   t2   = (const int*)  d_in[5];
    const float* A0   = (const float*)d_in[6];
    const float* A1   = (const float*)d_in[7];
    const float* E0   = (const float*)d_in[8];
    const float* E1   = (const float*)d_in[9];
    const float* W_fe = (const float*)d_in[10];
    const float* b_fe = (const float*)d_in[11];
    const float* W_x  = (const float*)d_in[12];
    const float* W_h  = (const float*)d_in[13];
    const float* W_e  = (const float*)d_in[14];
    const float* W_g  = (const float*)d_in[15];
    const float* b_g  = (const float*)d_in[16];
    const float* b_r  = (const float*)d_in[17];

    float *pooled, *h1, *bias;
    unsigned *Wc, *Whc, *Wgc;
    cudaGetSymbolAddress((void**)&pooled, g_pooled);
    cudaGetSymbolAddress((void**)&h1,     g_h1);
    cudaGetSymbolAddress((void**)&Wc,     g_Wc);
    cudaGetSymbolAddress((void**)&Whc,    g_Whc);
    cudaGetSymbolAddress((void**)&Wgc,    g_Wgc);
    cudaGetSymbolAddress((void**)&bias,   g_bias);

    const int SMEMSZ = (128 * H2_STRIDE + 2 * 128 * XS_STRIDE + 2 * 16 * WK_STRIDE) * 4
                     + (4 * 128 + 128 + 128 + 128) * 4;   // 109,056 B (2 CTAs/SM)
    cudaFuncSetAttribute(fused_level, cudaFuncAttributeMaxDynamicSharedMemorySize, SMEMSZ);

    // fold W_fe/b_fe into per-level weights; pre-convert weights to tf32
    prep_wc<<<3 * 128, 128>>>(W_fe, W_x);
    prep_bias<<<3, 128>>>(b_fe, W_x, b_r);
    prep_cvt<<<128, 256>>>(W_h, W_g);

    // level 2 + level 1 GNN fused: x2 -> h2 (smem) -> gate/mix -> relu GEMM -> pooled1
    fused_level<<<PB_N2 / 128, 256, SMEMSZ>>>(
        x2, t2, W_x + 2 * 132 * 128 + 128 * 128, Wc + 2 * 128 * 128, bias + 2 * 128,
        nullptr, A1, E1, W_e + 8, Wgc + 128 * 128, b_g + 128, pooled);

    // h1 = tanh(x1 @ Wc1 + pooled1 @ W_h1 + bias1 + typerow)
    gemm_tanh<<<PB_N1 / 128, 256>>>(
        x1, Wc + 128 * 128, pooled, Whc + 128 * 128,
        bias + 128, W_x + 132 * 128 + 128 * 128, t1, h1);

    // level 0 GNN fused (child hidden loaded from h1)
    fused_level<<<PB_N1 / 128, 256, SMEMSZ>>>(
        nullptr, nullptr, nullptr, nullptr, nullptr,
        h1, A0, E0, W_e, Wgc, b_g, pooled);

    // roots: h0 -> d_out
    gemm_tanh<<<PB_N0 / 128, 256>>>(
        x0, Wc, pooled, Whc,
        bias, W_x + 128 * 128, t0, (float*)d_out);
}

// round 10
// speedup vs baseline: 2.3982x; 1.0528x over previous
#include <cuda_runtime.h>
#include <math.h>

// Problem constants
#define PB_N0 2048
#define PB_N1 32768
#define PB_N2 524288
#define PB_C  16
#define PB_D  128
#define PB_H  128
#define PB_ED 8

#define H2_STRIDE 132   // tile stride: A-fragment reads conflict-free (4g+tg)
#define WK_STRIDE 136   // weight-chunk stride: B-fragment reads conflict-free (8tg+g)

// ---------------- scratch (device globals; no runtime allocation) ----------
__device__ float    g_pooled[(size_t)PB_N1 * PB_H];  // 16.8 MB (reused at level 0)
__device__ float    g_h1[(size_t)PB_N1 * PB_H];      // 16.8 MB
__device__ unsigned g_Wc[3 * PB_D * PB_H];           // tf32 bits: W_fe @ W_x[l][:128]
__device__ unsigned g_Whc[2 * PB_H * PB_H];          // tf32 bits: W_h levels 0,1
__device__ unsigned g_Wgc[2 * PB_H * PB_H];          // tf32 bits: W_g levels 0,1
__device__ float    g_bias[3 * PB_H];                // b_fe @ W_x[l][:128] + b_r[l]

// ---------------- tf32 / math helpers ---------------------------------------
__device__ __forceinline__ unsigned f2tf(float f) {
    unsigned r; asm("cvt.rna.tf32.f32 %0, %1;" : "=r"(r) : "f"(f)); return r;
}
__device__ __forceinline__ void mma8(float4& d, const unsigned a[4],
                                     unsigned b0, unsigned b1) {
    asm volatile(
        "mma.sync.aligned.m16n8k8.row.col.f32.tf32.tf32.f32 "
        "{%0,%1,%2,%3},{%4,%5,%6,%7},{%8,%9},{%0,%1,%2,%3};"
        : "+f"(d.x), "+f"(d.y), "+f"(d.z), "+f"(d.w)
        : "r"(a[0]), "r"(a[1]), "r"(a[2]), "r"(a[3]), "r"(b0), "r"(b1));
}
__device__ __forceinline__ float fast_tanh(float x) {
    float e = __expf(2.f * x);
    return 1.f - __fdividef(2.f, e + 1.f);
}

// ---------------- whole-tile preload: fp32 global -> tf32 smem (stride 132) -
__device__ __forceinline__ void loadTile(unsigned* dst, const float* src,
                                         size_t rowbase, int t) {
    #pragma unroll
    for (int u = 0; u < 16; ++u) {
        int f = t + u * 256; int r = f >> 5, c4 = (f & 31) * 4;
        float4 v = *(const float4*)(src + (rowbase + r) * 128 + c4);
        uint4 w;
        w.x = f2tf(v.x); w.y = f2tf(v.y); w.z = f2tf(v.z); w.w = f2tf(v.w);
        *(uint4*)(dst + r * H2_STRIDE + c4) = w;
    }
}

// ---------------- W chunk staging (tf32 bits, raw uint4) --------------------
__device__ __forceinline__ void loadWc(const unsigned* W, int kb,
                                       int t, uint4& wa, uint4& wb) {
    int f = t, r = f >> 5, c4 = (f & 31) * 4;
    wa = *(const uint4*)(W + (size_t)(kb + r) * 128 + c4);
    f = t + 256; r = f >> 5; c4 = (f & 31) * 4;
    wb = *(const uint4*)(W + (size_t)(kb + r) * 128 + c4);
}
__device__ __forceinline__ void storeWc(unsigned* Wb, int t,
                                        const uint4& wa, const uint4& wb) {
    int f = t, r = f >> 5, c4 = (f & 31) * 4;
    *(uint4*)(Wb + r * WK_STRIDE + c4) = wa;
    f = t + 256; r = f >> 5; c4 = (f & 31) * 4;
    *(uint4*)(Wb + r * WK_STRIDE + c4) = wb;
}

// one 16-K mma step; A from full tile T (stride 132) at K offset kb
__device__ __forceinline__ void mma_chunk_t(float4 acc[4][4],
                                            const unsigned* T, int kb,
                                            const unsigned* Wb,
                                            int warpM, int warpN, int g, int tg) {
    #pragma unroll
    for (int ks = 0; ks < 2; ++ks) {
        int k0 = kb + ks * 8;
        unsigned a[4][4], b[4][2];
        #pragma unroll
        for (int i = 0; i < 4; ++i) {
            int rb = warpM * 64 + i * 16;
            a[i][0] = T[(rb + g) * H2_STRIDE + k0 + tg];
            a[i][1] = T[(rb + g + 8) * H2_STRIDE + k0 + tg];
            a[i][2] = T[(rb + g) * H2_STRIDE + k0 + tg + 4];
            a[i][3] = T[(rb + g + 8) * H2_STRIDE + k0 + tg + 4];
        }
        #pragma unroll
        for (int j = 0; j < 4; ++j) {
            int col = warpN * 32 + j * 8 + g;
            b[j][0] = Wb[(ks * 8 + tg) * WK_STRIDE + col];
            b[j][1] = Wb[(ks * 8 + tg + 4) * WK_STRIDE + col];
        }
        #pragma unroll
        for (int i = 0; i < 4; ++i)
            #pragma unroll
            for (int j = 0; j < 4; ++j) mma8(acc[i][j], a[i], b[j][0], b[j][1]);
    }
}

// ---------------- prep: Wc[l] = tf32(W_fe @ W_x[l][0:128,:]) ----------------
__global__ void prep_wc(const float* __restrict__ W_fe,
                        const float* __restrict__ W_x) {
    int l = blockIdx.x >> 7;
    int d = blockIdx.x & 127;
    int h = threadIdx.x;
    const float* wx = W_x + (size_t)l * 132 * 128;
    float acc = 0.f;
    #pragma unroll 8
    for (int k = 0; k < 128; ++k)
        acc += W_fe[d * 128 + k] * wx[k * 128 + h];
    g_Wc[((size_t)l * 128 + d) * 128 + h] = f2tf(acc);
}

__global__ void prep_bias(const float* __restrict__ b_fe,
                          const float* __restrict__ W_x,
                          const float* __restrict__ b_r) {
    int l = blockIdx.x;
    int h = threadIdx.x;
    const float* wx = W_x + (size_t)l * 132 * 128;
    float acc = b_r[l * 128 + h];
    #pragma unroll 8
    for (int d = 0; d < 128; ++d)
        acc += b_fe[d] * wx[d * 128 + h];
    g_bias[l * 128 + h] = acc;
}

__global__ void prep_cvt(const float* __restrict__ Wh,
                         const float* __restrict__ Wg) {
    int i = blockIdx.x * 256 + threadIdx.x;   // 0 .. 32767
    g_Whc[i] = f2tf(Wh[i]);
    g_Wgc[i] = f2tf(Wg[i]);
}

// ============================================================================
// fused_level: per block 128 child rows = 8 parents (warp w <-> parent w).
// X tile preloaded whole into h2s; phase A reads A-fragments from it in place,
// then tanh epilogue overwrites h2s with child_h.
// ============================================================================
__global__ void __launch_bounds__(256, 2)
fused_level(const float* __restrict__ xin, const int* __restrict__ tvec,
            const float* __restrict__ tapg, const unsigned* __restrict__ Wc,
            const float* __restrict__ biasg,
            const float* __restrict__ hin,
            const float* __restrict__ Ag, const float* __restrict__ Eg,
            const float* __restrict__ Weg,
            const unsigned* __restrict__ Wg, const float* __restrict__ bgg,
            float* __restrict__ pooled)
{
    extern __shared__ unsigned char smraw[];
    unsigned* h2s = (unsigned*)smraw;                       // [128][132]
    unsigned* Wks = h2s + 128 * H2_STRIDE;                  // [2][16][136]
    float* taps   = (float*)(Wks + 2 * 16 * WK_STRIDE);     // [4][128]
    float* bgs    = taps + 4 * 128;                         // [128]
    float* biass  = bgs + 128;                              // [128]
    int*   ts     = (int*)(biass + 128);                    // [128]

    const int t = threadIdx.x;
    const int lane = t & 31, wid = t >> 5;
    const int warpM = wid >> 2, warpN = wid & 3;
    const int g = lane >> 2, tg = lane & 3;
    const size_t rowbase = (size_t)blockIdx.x * 128;

    if (t < 128) bgs[t] = bgg[t];

    float4 acc[4][4];
    float gg[2][2][2];   // [c8][k8][k4] gate values for this lane's parent

    if (xin) {
        if (t < 128) { biass[t] = biasg[t]; ts[t] = tvec[rowbase + t]; }
        taps[t] = tapg[t]; taps[t + 256] = tapg[t + 256];

        // preload full X tile into h2s (tf32 bits)
        loadTile(h2s, xin, rowbase, t);

        #pragma unroll
        for (int i = 0; i < 4; ++i)
            #pragma unroll
            for (int j = 0; j < 4; ++j) acc[i][j] = make_float4(0.f, 0.f, 0.f, 0.f);

        uint4 wa, wb;
        loadWc(Wc, 0, t, wa, wb);
        #pragma unroll
        for (int it = 0; it < 8; ++it) {
            unsigned* Wb = Wks + (it & 1) * 16 * WK_STRIDE;
            storeWc(Wb, t, wa, wb);
            __syncthreads();            // covers tile visibility at it==0 too
            if (it < 7) loadWc(Wc, (it + 1) * 16, t, wa, wb);
            mma_chunk_t(acc, h2s, it * 16, Wb, warpM, warpN, g, tg);
        }

        // gates (register-resident; no h2s access)
        {
            const size_t ebase = (size_t)blockIdx.x * 2048 + wid * 256;
            float we0 = Weg[0], we1 = Weg[1], we2 = Weg[2], we3 = Weg[3];
            float we4 = Weg[4], we5 = Weg[5], we6 = Weg[6], we7 = Weg[7];
            #pragma unroll
            for (int c8 = 0; c8 < 2; ++c8)
                #pragma unroll
                for (int k8 = 0; k8 < 2; ++k8)
                    #pragma unroll
                    for (int k4 = 0; k4 < 2; ++k4) {
                        int c = g + 8 * c8, k = tg + 4 * k4 + 8 * k8;
                        const float* e = Eg + (ebase + c * 16 + k) * 8;
                        float4 e0 = *(const float4*)(e);
                        float4 e1 = *(const float4*)(e + 4);
                        float s = e0.x * we0 + e0.y * we1 + e0.z * we2 + e0.w * we3
                                + e1.x * we4 + e1.y * we5 + e1.z * we6 + e1.w * we7;
                        gg[c8][k8][k4] = Ag[ebase + c * 16 + k] / (1.f + __expf(-s));
                    }
        }

        __syncthreads();   // all X fragment reads done before overwriting h2s

        // epilogue: fast tanh -> h2s (tf32 bits)
        #pragma unroll
        for (int i = 0; i < 4; ++i) {
            int r0 = warpM * 64 + i * 16 + g, r1 = r0 + 8;
            const float* tap0 = taps + ts[r0] * 128;
            const float* tap1 = taps + ts[r1] * 128;
            #pragma unroll
            for (int j = 0; j < 4; ++j) {
                int c0 = warpN * 32 + j * 8 + tg * 2;
                h2s[r0 * H2_STRIDE + c0]     = f2tf(fast_tanh(acc[i][j].x + biass[c0]     + tap0[c0]));
                h2s[r0 * H2_STRIDE + c0 + 1] = f2tf(fast_tanh(acc[i][j].y + biass[c0 + 1] + tap0[c0 + 1]));
                h2s[r1 * H2_STRIDE + c0]     = f2tf(fast_tanh(acc[i][j].z + biass[c0]     + tap1[c0]));
                h2s[r1 * H2_STRIDE + c0 + 1] = f2tf(fast_tanh(acc[i][j].w + biass[c0 + 1] + tap1[c0 + 1]));
            }
        }
    } else {
        // load child hidden tile from global (cvt + STS.128)
        loadTile(h2s, hin, rowbase, t);
        {
            const size_t ebase = (size_t)blockIdx.x * 2048 + wid * 256;
            float we0 = Weg[0], we1 = Weg[1], we2 = Weg[2], we3 = Weg[3];
            float we4 = Weg[4], we5 = Weg[5], we6 = Weg[6], we7 = Weg[7];
            #pragma unroll
            for (int c8 = 0; c8 < 2; ++c8)
                #pragma unroll
                for (int k8 = 0; k8 < 2; ++k8)
                    #pragma unroll
                    for (int k4 = 0; k4 < 2; ++k4) {
                        int c = g + 8 * c8, k = tg + 4 * k4 + 8 * k8;
                        const float* e = Eg + (ebase + c * 16 + k) * 8;
                        float4 e0 = *(const float4*)(e);
                        float4 e1 = *(const float4*)(e + 4);
                        float s = e0.x * we0 + e0.y * we1 + e0.z * we2 + e0.w * we3
                                + e1.x * we4 + e1.y * we5 + e1.z * we6 + e1.w * we7;
                        gg[c8][k8][k4] = Ag[ebase + c * 16 + k] / (1.f + __expf(-s));
                    }
        }
    }
    __syncthreads();   // h2s (child hidden) complete

    // Phase C: per-parent mix M_p = G_p @ child_h_p  (warp wid = parent)
    {
        float4 macc[16];
        #pragma unroll
        for (int j = 0; j < 16; ++j) macc[j] = make_float4(0.f, 0.f, 0.f, 0.f);
        int p = wid;
        #pragma unroll
        for (int ks = 0; ks < 2; ++ks) {
            unsigned a[4];
            a[0] = f2tf(gg[0][ks][0]);
            a[1] = f2tf(gg[1][ks][0]);
            a[2] = f2tf(gg[0][ks][1]);
            a[3] = f2tf(gg[1][ks][1]);
            #pragma unroll
            for (int j = 0; j < 16; ++j) {
                unsigned b0 = h2s[(p * 16 + ks * 8 + tg) * H2_STRIDE + j * 8 + g];
                unsigned b1 = h2s[(p * 16 + ks * 8 + tg + 4) * H2_STRIDE + j * 8 + g];
                mma8(macc[j], a, b0, b1);
            }
        }
        __syncwarp();
        #pragma unroll
        for (int j = 0; j < 16; ++j) {
            int c0 = j * 8 + tg * 2;
            h2s[(p * 16 + g) * H2_STRIDE + c0]         = f2tf(macc[j].x);
            h2s[(p * 16 + g) * H2_STRIDE + c0 + 1]     = f2tf(macc[j].y);
            h2s[(p * 16 + g + 8) * H2_STRIDE + c0]     = f2tf(macc[j].z);
            h2s[(p * 16 + g + 8) * H2_STRIDE + c0 + 1] = f2tf(macc[j].w);
        }
    }
    __syncthreads();

    // Phase D: Hc = relu(M @ Wg + bg); maxpool over each parent's 16 rows
    #pragma unroll
    for (int i = 0; i < 4; ++i)
        #pragma unroll
        for (int j = 0; j < 4; ++j) acc[i][j] = make_float4(0.f, 0.f, 0.f, 0.f);

    {
        uint4 wa, wb;
        loadWc(Wg, 0, t, wa, wb);
        #pragma unroll
        for (int it = 0; it < 8; ++it) {
            unsigned* Wb = Wks + (it & 1) * 16 * WK_STRIDE;
            storeWc(Wb, t, wa, wb);
            __syncthreads();
            if (it < 7) loadWc(Wg, (it + 1) * 16, t, wa, wb);
            mma_chunk_t(acc, h2s, it * 16, Wb, warpM, warpN, g, tg);
        }
    }

    // relu + 16-row maxpool (m-tile i == parent warpM*4+i exactly)
    #pragma unroll
    for (int i = 0; i < 4; ++i) {
        size_t parent = (size_t)blockIdx.x * 8 + warpM * 4 + i;
        #pragma unroll
        for (int j = 0; j < 4; ++j) {
            int c0 = warpN * 32 + j * 8 + tg * 2;
            float b0 = bgs[c0], b1 = bgs[c0 + 1];
            float v0 = fmaxf(fmaxf(acc[i][j].x + b0, acc[i][j].z + b0), 0.f);
            float v1 = fmaxf(fmaxf(acc[i][j].y + b1, acc[i][j].w + b1), 0.f);
            #pragma unroll
            for (int off = 16; off >= 4; off >>= 1) {
                v0 = fmaxf(v0, __shfl_xor_sync(0xffffffffu, v0, off));
                v1 = fmaxf(v1, __shfl_xor_sync(0xffffffffu, v1, off));
            }
            if (lane < 4)
                *(float2*)(pooled + parent * 128 + c0) = make_float2(v0, v1);
        }
    }
}

// ============================================================================
// gemm_tanh: out = tanh(A0 @ W0 + A1 @ W1 + bias + typerow[t]) , tf32 mma
// Per-segment whole-tile preload; W double-buffered per chunk.
// ============================================================================
__global__ void __launch_bounds__(256, 2)
gemm_tanh(const float* __restrict__ A0g, const unsigned* __restrict__ W0,
          const float* __restrict__ A1g, const unsigned* __restrict__ W1,
          const float* __restrict__ biasg, const float* __restrict__ tapg,
          const int* __restrict__ tvec, float* __restrict__ out)
{
    extern __shared__ unsigned char smraw[];
    unsigned* Xt  = (unsigned*)smraw;                       // [128][132]
    unsigned* Wks = Xt + 128 * H2_STRIDE;                   // [2][16][136]
    float* taps   = (float*)(Wks + 2 * 16 * WK_STRIDE);     // [4][128]
    float* biass  = taps + 4 * 128;                         // [128]
    int*   ts     = (int*)(biass + 128);                    // [128]

    const int t = threadIdx.x;
    const int lane = t & 31, wid = t >> 5;
    const int warpM = wid >> 2, warpN = wid & 3;
    const int g = lane >> 2, tg = lane & 3;
    const size_t rowbase = (size_t)blockIdx.x * 128;

    if (t < 128) { biass[t] = biasg[t]; ts[t] = tvec[rowbase + t]; }
    taps[t] = tapg[t]; taps[t + 256] = tapg[t + 256];

    const float* Aseg[2] = {A0g, A1g};
    const unsigned* Wseg[2] = {W0, W1};

    float4 acc[4][4];
    #pragma unroll
    for (int i = 0; i < 4; ++i)
        #pragma unroll
        for (int j = 0; j < 4; ++j) acc[i][j] = make_float4(0.f, 0.f, 0.f, 0.f);

    #pragma unroll
    for (int seg = 0; seg < 2; ++seg) {
        __syncthreads();                 // prior segment's tile reads done
        loadTile(Xt, Aseg[seg], rowbase, t);
        uint4 wa, wb;
        loadWc(Wseg[seg], 0, t, wa, wb);
        #pragma unroll
        for (int it = 0; it < 8; ++it) {
            unsigned* Wb = Wks + (it & 1) * 16 * WK_STRIDE;
            storeWc(Wb, t, wa, wb);
            __syncthreads();             // covers tile visibility at it==0
            if (it < 7) loadWc(Wseg[seg], (it + 1) * 16, t, wa, wb);
            mma_chunk_t(acc, Xt, it * 16, Wb, warpM, warpN, g, tg);
        }
    }

    #pragma unroll
    for (int i = 0; i < 4; ++i) {
        int r0 = warpM * 64 + i * 16 + g, r1 = r0 + 8;
        const float* tap0 = taps + ts[r0] * 128;
        const float* tap1 = taps + ts[r1] * 128;
        #pragma unroll
        for (int j = 0; j < 4; ++j) {
            int c0 = warpN * 32 + j * 8 + tg * 2;
            float o0 = fast_tanh(acc[i][j].x + biass[c0]     + tap0[c0]);
            float o1 = fast_tanh(acc[i][j].y + biass[c0 + 1] + tap0[c0 + 1]);
            float o2 = fast_tanh(acc[i][j].z + biass[c0]     + tap1[c0]);
            float o3 = fast_tanh(acc[i][j].w + biass[c0 + 1] + tap1[c0 + 1]);
            *(float2*)(out + (rowbase + r0) * 128 + c0) = make_float2(o0, o1);
            *(float2*)(out + (rowbase + r1) * 128 + c0) = make_float2(o2, o3);
        }
    }
}

// ---------------- launch -----------------------------------------------
extern "C" void kernel_launch(void* const* d_in, const int* in_sizes, int n_in,
                              void* d_out, int out_size) {
    const float* x0   = (const float*)d_in[0];
    const float* x1   = (const float*)d_in[1];
    const float* x2   = (const float*)d_in[2];
    const int*   t0   = (const int*)  d_in[3];
    const int*   t1   = (const int*)  d_in[4];
    const int*   t2   = (const int*)  d_in[5];
    const float* A0   = (const float*)d_in[6];
    const float* A1   = (const float*)d_in[7];
    const float* E0   = (const float*)d_in[8];
    const float* E1   = (const float*)d_in[9];
    const float* W_fe = (const float*)d_in[10];
    const float* b_fe = (const float*)d_in[11];
    const float* W_x  = (const float*)d_in[12];
    const float* W_h  = (const float*)d_in[13];
    const float* W_e  = (const float*)d_in[14];
    const float* W_g  = (const float*)d_in[15];
    const float* b_g  = (const float*)d_in[16];
    const float* b_r  = (const float*)d_in[17];

    float *pooled, *h1, *bias;
    unsigned *Wc, *Whc, *Wgc;
    cudaGetSymbolAddress((void**)&pooled, g_pooled);
    cudaGetSymbolAddress((void**)&h1,     g_h1);
    cudaGetSymbolAddress((void**)&Wc,     g_Wc);
    cudaGetSymbolAddress((void**)&Whc,    g_Whc);
    cudaGetSymbolAddress((void**)&Wgc,    g_Wgc);
    cudaGetSymbolAddress((void**)&bias,   g_bias);

    const int SMEM_FL = (128 * H2_STRIDE + 2 * 16 * WK_STRIDE) * 4
                      + (4 * 128 + 128 + 128 + 128) * 4;   // 88,576 B
    const int SMEM_GT = (128 * H2_STRIDE + 2 * 16 * WK_STRIDE) * 4
                      + (4 * 128 + 128 + 128) * 4;         // 88,064 B
    cudaFuncSetAttribute(fused_level, cudaFuncAttributeMaxDynamicSharedMemorySize, SMEM_FL);
    cudaFuncSetAttribute(gemm_tanh,   cudaFuncAttributeMaxDynamicSharedMemorySize, SMEM_GT);

    // fold W_fe/b_fe into per-level weights; pre-convert weights to tf32
    prep_wc<<<3 * 128, 128>>>(W_fe, W_x);
    prep_bias<<<3, 128>>>(b_fe, W_x, b_r);
    prep_cvt<<<128, 256>>>(W_h, W_g);

    // level 2 + level 1 GNN fused: x2 -> h2 (smem) -> gate/mix -> relu GEMM -> pooled1
    fused_level<<<PB_N2 / 128, 256, SMEM_FL>>>(
        x2, t2, W_x + 2 * 132 * 128 + 128 * 128, Wc + 2 * 128 * 128, bias + 2 * 128,
        nullptr, A1, E1, W_e + 8, Wgc + 128 * 128, b_g + 128, pooled);

    // h1 = tanh(x1 @ Wc1 + pooled1 @ W_h1 + bias1 + typerow)
    gemm_tanh<<<PB_N1 / 128, 256, SMEM_GT>>>(
        x1, Wc + 128 * 128, pooled, Whc + 128 * 128,
        bias + 128, W_x + 132 * 128 + 128 * 128, t1, h1);

    // level 0 GNN fused (child hidden loaded from h1)
    fused_level<<<PB_N1 / 128, 256, SMEM_FL>>>(
        nullptr, nullptr, nullptr, nullptr, nullptr,
        h1, A0, E0, W_e, Wgc, b_g, pooled);

    // roots: h0 -> d_out
    gemm_tanh<<<PB_N0 / 128, 256, SMEM_GT>>>(
        x0, Wc, pooled, Whc,
        bias, W_x + 128 * 128, t0, (float*)d_out);
}